// round 4
// baseline (speedup 1.0000x reference)
#include <cuda_runtime.h>
#include <cuda_bf16.h>
#include <cstdint>

#define Hd   64
#define Wd   64
#define HW   4096
#define Bd   4
#define Cd   256
#define COd  256
#define KDIM 2304
#define NTOT 16384
#define NGRP 16
#define CPG  16

// GEMM tiling
#define BM 128
#define BN 128
#define BK 32
#define NSTG   (KDIM / BK)     // 72 stages, single K sweep
// stage layout (bytes): Ah[128][80] Al[128][80] Bh[32][272] Bl[32][272]
#define A_ROW_B  80
#define B_ROW_B  272
#define AH_OFF   0
#define AL_OFF   10240
#define BH_OFF   20480
#define BL_OFF   29184
#define STAGE_B  37888
#define NBUF     4
// smem: weight/index tables first, then 4 stage buffers
#define TW_OFF   0
#define TI_OFF   18432
#define TABLE_B  27648
#define SMEM_TOTAL (TABLE_B + NBUF * STAGE_B)   // 179200

// weights split to bf16 hi/lo, [256][2304]
__device__ __align__(256) __nv_bfloat16 g_wh[COd * KDIM];
__device__ __align__(256) __nv_bfloat16 g_wl[COd * KDIM];
// bilinear tables per (kk, n): weights (float4) and packed indices (uint2)
__device__ __align__(256) float4 g_w4[9 * NTOT];
__device__ __align__(256) uint2  g_i4[9 * NTOT];
// groupnorm partials + nothing else
__device__ float2 g_part[512];

// ---------------------------------------------------------------------------
__device__ __forceinline__ uint32_t smem_u32(const void* p) {
    uint32_t a;
    asm("{ .reg .u64 t; cvta.to.shared.u64 t, %1; cvt.u32.u64 %0, t; }" : "=r"(a) : "l"(p));
    return a;
}
#define CP_ASYNC(dst, src) \
    asm volatile("cp.async.cg.shared.global [%0], [%1], 16;" :: "r"(dst), "l"(src))
#define CP_COMMIT() asm volatile("cp.async.commit_group;")
#define CP_WAIT(n)  asm volatile("cp.async.wait_group %0;" :: "n"(n))

#define LDMATRIX_X4(r0, r1, r2, r3, a) \
    asm volatile("ldmatrix.sync.aligned.m8n8.x4.shared.b16 {%0,%1,%2,%3}, [%4];" \
        : "=r"(r0), "=r"(r1), "=r"(r2), "=r"(r3) : "r"(a))
#define LDMATRIX_X4T(r0, r1, r2, r3, a) \
    asm volatile("ldmatrix.sync.aligned.m8n8.x4.trans.shared.b16 {%0,%1,%2,%3}, [%4];" \
        : "=r"(r0), "=r"(r1), "=r"(r2), "=r"(r3) : "r"(a))

#define MMA_BF16(d, a, b0v, b1v) \
    asm volatile("mma.sync.aligned.m16n8k16.row.col.f32.bf16.bf16.f32 " \
        "{%0,%1,%2,%3}, {%4,%5,%6,%7}, {%8,%9}, {%0,%1,%2,%3};" \
        : "+f"((d)[0]), "+f"((d)[1]), "+f"((d)[2]), "+f"((d)[3]) \
        : "r"((a)[0]), "r"((a)[1]), "r"((a)[2]), "r"((a)[3]), "r"(b0v), "r"(b1v))

// ---------------------------------------------------------------------------
// Kernel 1: prep — bilinear weight/index tables + weight hi/lo split
// grid (64, 9), block 256
// ---------------------------------------------------------------------------
__global__ __launch_bounds__(256) void prep_kernel(
    const float* __restrict__ off, const float* __restrict__ mask,
    const float* __restrict__ wsrc)
{
    const int n  = blockIdx.x * 256 + threadIdx.x;   // 0..16383
    const int k  = blockIdx.y;                        // kk 0..8
    const int b  = n >> 12;
    const int hw = n & 4095;
    const int h  = hw >> 6;
    const int w  = hw & 63;

    const float dy = off[((b * 18 + 2 * k)     << 12) + hw];
    const float dx = off[((b * 18 + 2 * k + 1) << 12) + hw];
    const float m  = mask[((b * 9 + k)         << 12) + hw];

    const float y = (float)h + (float)(k / 3 - 1) + dy;
    const float x = (float)w + (float)(k % 3 - 1) + dx;
    const float y0f = floorf(y), x0f = floorf(x);
    const int   y0 = (int)y0f,  x0 = (int)x0f;
    const float wy1 = y - y0f, wx1 = x - x0f;
    const float wy0 = 1.0f - wy1, wx0 = 1.0f - wx1;

    const bool vy0 = (y0 >= 0) && (y0 < Hd);
    const bool vy1 = (y0 + 1 >= 0) && (y0 + 1 < Hd);
    const bool vx0 = (x0 >= 0) && (x0 < Wd);
    const bool vx1 = (x0 + 1 >= 0) && (x0 + 1 < Wd);

    const float w00 = (vy0 && vx0) ? wy0 * wx0 * m : 0.0f;
    const float w01 = (vy0 && vx1) ? wy0 * wx1 * m : 0.0f;
    const float w10 = (vy1 && vx0) ? wy1 * wx0 * m : 0.0f;
    const float w11 = (vy1 && vx1) ? wy1 * wx1 * m : 0.0f;

    const uint32_t i00 = (vy0 && vx0) ? (uint32_t)(y0       * Wd + x0    ) : 0u;
    const uint32_t i01 = (vy0 && vx1) ? (uint32_t)(y0       * Wd + x0 + 1) : 0u;
    const uint32_t i10 = (vy1 && vx0) ? (uint32_t)((y0 + 1) * Wd + x0    ) : 0u;
    const uint32_t i11 = (vy1 && vx1) ? (uint32_t)((y0 + 1) * Wd + x0 + 1) : 0u;

    g_w4[k * NTOT + n] = make_float4(w00, w01, w10, w11);
    g_i4[k * NTOT + n] = make_uint2(i00 | (i01 << 16), i10 | (i11 << 16));

    // weight split (kk==0 blocks only): 16384 threads x 36 = 589824 elems
    if (k == 0) {
#pragma unroll 4
        for (int r = 0; r < 36; ++r) {
            const int j = n + r * NTOT;
            float v = wsrc[j];
            __nv_bfloat16 hi = __float2bfloat16(v);
            g_wh[j] = hi;
            g_wl[j] = __float2bfloat16(v - __bfloat162float(hi));
        }
    }
}

// ---------------------------------------------------------------------------
// Kernel 2: fused sampling + bf16x3 GEMM via mma.sync
// grid (2 m-tiles, 128 n-tiles), 256 threads.
// warps 0-3: MMA (64x64 warp tiles); warps 4-7: loaders (gather B, cp.async A)
// ---------------------------------------------------------------------------
__global__ __launch_bounds__(256, 1) void gemm_fused(
    const float* __restrict__ input, const float* __restrict__ bias,
    float* __restrict__ out)
{
    extern __shared__ char smem[];
    const uint32_t sb = smem_u32(smem);
    const int tid = threadIdx.x;
    const int wid = tid >> 5;
    const int lid = tid & 31;
    const int m0  = blockIdx.x * BM;
    const int n0  = blockIdx.y * BN;
    const int b   = n0 >> 12;
    const float* __restrict__ inb = input + (size_t)(b * Cd) * HW;

    // ---- cooperative table load: 9 x 128 entries for this CTA's n-window
    for (int i = tid; i < 9 * 128; i += 256) {
        const int kk = i >> 7, nl = i & 127;
        *(float4*)(smem + TW_OFF + i * 16) = g_w4[kk * NTOT + n0 + nl];
        *(uint2*)(smem + TI_OFF + i * 8)   = g_i4[kk * NTOT + n0 + nl];
    }
    __syncthreads();

    const bool is_mma = (wid < 4);
    const int  wm = wid >> 1;        // MMA: 0..1
    const int  wn = wid & 1;         // MMA: 0..1
    const int  lt = (wid - 4) * 32 + lid;   // loader: 0..127

    float acc[4][8][4];
    if (is_mma) {
#pragma unroll
        for (int i = 0; i < 4; ++i)
#pragma unroll
            for (int j = 0; j < 8; ++j)
#pragma unroll
                for (int r = 0; r < 4; ++r) acc[i][j][r] = 0.0f;
    }

    // ---- loader lambdas (expressed as macros via code blocks)
#define LOAD_A_STAGE(S) do { \
    const int _k0 = (S) * BK; \
    const uint32_t _dst0 = sb + TABLE_B + (uint32_t)((S) & 3) * STAGE_B; \
    _Pragma("unroll") \
    for (int _j = 0; _j < 8; ++_j) { \
        const int _c = lt + _j * 128; \
        const int _row = (_c >> 2) & 127, _seg = _c & 3; \
        const __nv_bfloat16* _src = (_c < 512 ? g_wh : g_wl) + (m0 + _row) * KDIM + _k0 + _seg * 8; \
        const uint32_t _dst = _dst0 + (_c < 512 ? AH_OFF : AL_OFF) + _row * A_ROW_B + _seg * 16; \
        CP_ASYNC(_dst, _src); \
    } } while (0)

#define FILL_B_STAGE(S) do { \
    const int _k0 = (S) * BK; \
    char* _sbuf = smem + TABLE_B + (size_t)((S) & 3) * STAGE_B; \
    _Pragma("unroll") \
    for (int _base = 0; _base < 32; _base += 8) { \
        float4 _wv[8]; float _g[8][4]; \
        _Pragma("unroll") \
        for (int _e = 0; _e < 8; ++_e) { \
            const int _k = _k0 + _base + _e; \
            const int _c = _k / 9; \
            const int _kk = _k - _c * 9; \
            const uint32_t _t = (uint32_t)(_kk * 128 + lt); \
            _wv[_e] = *(const float4*)(smem + TW_OFF + _t * 16); \
            const uint2 _iu = *(const uint2*)(smem + TI_OFF + _t * 8); \
            const float* _pl = inb + _c * HW; \
            _g[_e][0] = __ldg(_pl + (_iu.x & 0xFFFF)); \
            _g[_e][1] = __ldg(_pl + (_iu.x >> 16)); \
            _g[_e][2] = __ldg(_pl + (_iu.y & 0xFFFF)); \
            _g[_e][3] = __ldg(_pl + (_iu.y >> 16)); \
        } \
        _Pragma("unroll") \
        for (int _e = 0; _e < 8; ++_e) { \
            const int _krow = _base + _e; \
            float _v = _wv[_e].x * _g[_e][0] + _wv[_e].y * _g[_e][1] \
                     + _wv[_e].z * _g[_e][2] + _wv[_e].w * _g[_e][3]; \
            __nv_bfloat16 _hi = __float2bfloat16(_v); \
            __nv_bfloat16 _lo = __float2bfloat16(_v - __bfloat162float(_hi)); \
            *(__nv_bfloat16*)(_sbuf + BH_OFF + _krow * B_ROW_B + lt * 2) = _hi; \
            *(__nv_bfloat16*)(_sbuf + BL_OFF + _krow * B_ROW_B + lt * 2) = _lo; \
        } \
    } } while (0)

    // ---- prologue: loaders fill stages 0..2
    if (!is_mma) {
        for (int p = 0; p < 3; ++p) {
            LOAD_A_STAGE(p);
            FILL_B_STAGE(p);
            CP_COMMIT();
        }
        CP_WAIT(2);
    }
    __syncthreads();

    const uint32_t a_lane = (uint32_t)((lid & 15) * A_ROW_B + (lid >> 4) * 16);
    const uint32_t b_lane = (uint32_t)((lid & 15) * B_ROW_B + (lid >> 4) * 16);

    // ---- main loop
    for (int s = 0; s < NSTG; ++s) {
        if (is_mma) {
            const uint32_t sbuf = sb + TABLE_B + (uint32_t)(s & 3) * STAGE_B;
#pragma unroll
            for (int kkp = 0; kkp < 2; ++kkp) {
                uint32_t bfh[4][4];
#pragma unroll
                for (int j2 = 0; j2 < 4; ++j2) {
                    const uint32_t addr = sbuf + BH_OFF + (uint32_t)(kkp * 16) * B_ROW_B
                                        + (uint32_t)((wn * 64 + j2 * 16) * 2) + b_lane;
                    LDMATRIX_X4T(bfh[j2][0], bfh[j2][1], bfh[j2][2], bfh[j2][3], addr);
                }
                {   // Ah x Bh
                    uint32_t af[4][4];
#pragma unroll
                    for (int i = 0; i < 4; ++i) {
                        const uint32_t addr = sbuf + AH_OFF + (uint32_t)((wm * 64 + i * 16) * A_ROW_B)
                                            + (uint32_t)(kkp * 32) + a_lane;
                        LDMATRIX_X4(af[i][0], af[i][1], af[i][2], af[i][3], addr);
                    }
#pragma unroll
                    for (int i = 0; i < 4; ++i)
#pragma unroll
                        for (int j = 0; j < 8; ++j)
                            MMA_BF16(acc[i][j], af[i], bfh[j >> 1][(j & 1) * 2], bfh[j >> 1][(j & 1) * 2 + 1]);
                }
                {   // Al x Bh
                    uint32_t af[4][4];
#pragma unroll
                    for (int i = 0; i < 4; ++i) {
                        const uint32_t addr = sbuf + AL_OFF + (uint32_t)((wm * 64 + i * 16) * A_ROW_B)
                                            + (uint32_t)(kkp * 32) + a_lane;
                        LDMATRIX_X4(af[i][0], af[i][1], af[i][2], af[i][3], addr);
                    }
#pragma unroll
                    for (int i = 0; i < 4; ++i)
#pragma unroll
                        for (int j = 0; j < 8; ++j)
                            MMA_BF16(acc[i][j], af[i], bfh[j >> 1][(j & 1) * 2], bfh[j >> 1][(j & 1) * 2 + 1]);
                }
                {   // Ah x Bl
                    uint32_t bfl[4][4];
#pragma unroll
                    for (int j2 = 0; j2 < 4; ++j2) {
                        const uint32_t addr = sbuf + BL_OFF + (uint32_t)(kkp * 16) * B_ROW_B
                                            + (uint32_t)((wn * 64 + j2 * 16) * 2) + b_lane;
                        LDMATRIX_X4T(bfl[j2][0], bfl[j2][1], bfl[j2][2], bfl[j2][3], addr);
                    }
                    uint32_t af[4][4];
#pragma unroll
                    for (int i = 0; i < 4; ++i) {
                        const uint32_t addr = sbuf + AH_OFF + (uint32_t)((wm * 64 + i * 16) * A_ROW_B)
                                            + (uint32_t)(kkp * 32) + a_lane;
                        LDMATRIX_X4(af[i][0], af[i][1], af[i][2], af[i][3], addr);
                    }
#pragma unroll
                    for (int i = 0; i < 4; ++i)
#pragma unroll
                        for (int j = 0; j < 8; ++j)
                            MMA_BF16(acc[i][j], af[i], bfl[j >> 1][(j & 1) * 2], bfl[j >> 1][(j & 1) * 2 + 1]);
                }
            }
        } else {
            if (s + 3 < NSTG) {
                LOAD_A_STAGE(s + 3);
                FILL_B_STAGE(s + 3);
                CP_COMMIT();
                CP_WAIT(2);
            } else if (s + 2 < NSTG) {
                CP_WAIT(1);
            } else {
                CP_WAIT(0);
            }
        }
        __syncthreads();
    }

    // ---- epilogue
    if (is_mma) {
        const int hwb = n0 & 4095;
#pragma unroll
        for (int i = 0; i < 4; ++i) {
            const int o_lo = m0 + wm * 64 + i * 16 + (lid >> 2);
            const float bi0 = bias[o_lo];
            const float bi1 = bias[o_lo + 8];
#pragma unroll
            for (int j = 0; j < 8; ++j) {
                const int nc = hwb + wn * 64 + j * 8 + (lid & 3) * 2;
                float2 v0 = make_float2(acc[i][j][0] + bi0, acc[i][j][1] + bi0);
                float2 v1 = make_float2(acc[i][j][2] + bi1, acc[i][j][3] + bi1);
                *(float2*)(out + (((size_t)(b * COd + o_lo))     << 12) + nc) = v0;
                *(float2*)(out + (((size_t)(b * COd + o_lo + 8)) << 12) + nc) = v1;
            }
        }
    }
}

// ---------------------------------------------------------------------------
// Kernel 3: GroupNorm partial sums. grid 512 (8 blocks per (b,g))
// ---------------------------------------------------------------------------
__global__ __launch_bounds__(256) void stats_kernel(const float* __restrict__ out)
{
    const int bg   = blockIdx.x >> 3;
    const int part = blockIdx.x & 7;
    const float* p = out + (size_t)bg * 65536 + part * 8192;

    float s = 0.0f, ss = 0.0f;
#pragma unroll
    for (int it = 0; it < 8; ++it) {
        float4 v = *(const float4*)(p + (threadIdx.x + it * 256) * 4);
        s  += v.x + v.y + v.z + v.w;
        ss += v.x * v.x + v.y * v.y + v.z * v.z + v.w * v.w;
    }
    __shared__ float sh_s[256], sh_q[256];
    sh_s[threadIdx.x] = s; sh_q[threadIdx.x] = ss;
    __syncthreads();
    for (int st = 128; st > 0; st >>= 1) {
        if (threadIdx.x < st) {
            sh_s[threadIdx.x] += sh_s[threadIdx.x + st];
            sh_q[threadIdx.x] += sh_q[threadIdx.x + st];
        }
        __syncthreads();
    }
    if (threadIdx.x == 0) g_part[blockIdx.x] = make_float2(sh_s[0], sh_q[0]);
}

// ---------------------------------------------------------------------------
// Kernel 4: normalize in place (finalizes stats deterministically per block)
// ---------------------------------------------------------------------------
__global__ __launch_bounds__(256) void norm_kernel(
    float* __restrict__ out, const float* __restrict__ gamma,
    const float* __restrict__ beta)
{
    const int fi0 = blockIdx.x << 10;     // 1024 floats per block
    const int o   = (fi0 >> 12) & 255;
    const int b   = fi0 >> 20;
    const int bg  = b * 16 + (o >> 4);

    float s = 0.0f, q = 0.0f;
#pragma unroll
    for (int i = 0; i < 8; ++i) {
        float2 pp = g_part[bg * 8 + i];
        s += pp.x; q += pp.y;
    }
    const float cnt = 65536.0f;
    const float mu  = s / cnt;
    const float var = q / cnt - mu * mu;
    const float inv = rsqrtf(var + 1e-5f);
    const float ga  = gamma[o] * inv;
    const float be  = beta[o] - mu * ga;

    const int idx = (fi0 >> 2) + threadIdx.x;
    float4 v = ((const float4*)out)[idx];
    v.x = v.x * ga + be; v.y = v.y * ga + be;
    v.z = v.z * ga + be; v.w = v.w * ga + be;
    ((float4*)out)[idx] = v;
}

// ---------------------------------------------------------------------------
extern "C" void kernel_launch(void* const* d_in, const int* in_sizes, int n_in,
                              void* d_out, int out_size)
{
    const float* input  = (const float*)d_in[0];
    const float* offset = (const float*)d_in[1];
    const float* mask   = (const float*)d_in[2];
    const float* weight = (const float*)d_in[3];
    const float* bias   = (const float*)d_in[4];
    const float* gamma  = (const float*)d_in[5];
    const float* beta   = (const float*)d_in[6];
    float* out = (float*)d_out;

    cudaFuncSetAttribute(gemm_fused, cudaFuncAttributeMaxDynamicSharedMemorySize, SMEM_TOTAL);

    dim3 gp(NTOT / 256, 9);
    prep_kernel<<<gp, 256>>>(offset, mask, weight);

    dim3 gg(COd / BM, NTOT / BN);
    gemm_fused<<<gg, 256, SMEM_TOTAL>>>(input, bias, out);

    stats_kernel<<<512, 256>>>(out);

    norm_kernel<<<Bd * COd * HW / 1024, 256>>>(out, gamma, beta);
}

// round 5
// speedup vs baseline: 1.5148x; 1.5148x over previous
#include <cuda_runtime.h>
#include <cuda_bf16.h>
#include <cstdint>

#define Hd   64
#define Wd   64
#define HW   4096
#define Bd   4
#define Cd   256
#define COd  256
#define KDIM 2304
#define NTOT 16384
#define NGRP 16
#define CPG  16

// GEMM tiling
#define BM 128
#define BN 128
#define BK 32
#define NSTG (KDIM / BK)       // 72 stages, single K sweep
// stage layout (bytes): Ah[128][80] Al[128][80] Bh[32][272] Bl[32][272]
#define A_ROW_B  80
#define B_ROW_B  272
#define AH_OFF   0
#define AL_OFF   10240
#define BH_OFF   20480
#define BL_OFF   29184
#define STAGE_B  37888
#define NBUF     2
#define SMEM_TOTAL (NBUF * STAGE_B)   // 75776

// im2col columns as bf16 hi/lo, layout [k=2304][n=16384]
__device__ __align__(256) __nv_bfloat16 g_colsh[(size_t)KDIM * NTOT];
__device__ __align__(256) __nv_bfloat16 g_colsl[(size_t)KDIM * NTOT];
// weights split to bf16 hi/lo, [256][2304]
__device__ __align__(256) __nv_bfloat16 g_wh[COd * KDIM];
__device__ __align__(256) __nv_bfloat16 g_wl[COd * KDIM];
// groupnorm partials
__device__ float2 g_part[512];

// ---------------------------------------------------------------------------
__device__ __forceinline__ uint32_t smem_u32(const void* p) {
    uint32_t a;
    asm("{ .reg .u64 t; cvta.to.shared.u64 t, %1; cvt.u32.u64 %0, t; }" : "=r"(a) : "l"(p));
    return a;
}
#define CP_ASYNC(dst, src) \
    asm volatile("cp.async.cg.shared.global [%0], [%1], 16;" :: "r"(dst), "l"(src))
#define CP_COMMIT() asm volatile("cp.async.commit_group;")
#define CP_WAIT(n)  asm volatile("cp.async.wait_group %0;" :: "n"(n))

#define LDMATRIX_X4(r0, r1, r2, r3, a) \
    asm volatile("ldmatrix.sync.aligned.m8n8.x4.shared.b16 {%0,%1,%2,%3}, [%4];" \
        : "=r"(r0), "=r"(r1), "=r"(r2), "=r"(r3) : "r"(a))
#define LDMATRIX_X4T(r0, r1, r2, r3, a) \
    asm volatile("ldmatrix.sync.aligned.m8n8.x4.trans.shared.b16 {%0,%1,%2,%3}, [%4];" \
        : "=r"(r0), "=r"(r1), "=r"(r2), "=r"(r3) : "r"(a))

#define MMA_BF16(d, a, b0v, b1v) \
    asm volatile("mma.sync.aligned.m16n8k16.row.col.f32.bf16.bf16.f32 " \
        "{%0,%1,%2,%3}, {%4,%5,%6,%7}, {%8,%9}, {%0,%1,%2,%3};" \
        : "+f"((d)[0]), "+f"((d)[1]), "+f"((d)[2]), "+f"((d)[3]) \
        : "r"((a)[0]), "r"((a)[1]), "r"((a)[2]), "r"((a)[3]), "r"(b0v), "r"(b1v))

// ---------------------------------------------------------------------------
// Kernel 0: split weights into bf16 hi/lo
// ---------------------------------------------------------------------------
__global__ __launch_bounds__(256) void wprep_kernel(const float* __restrict__ w) {
    int i = blockIdx.x * 256 + threadIdx.x;
    float v = w[i];
    __nv_bfloat16 hi = __float2bfloat16(v);
    g_wh[i] = hi;
    g_wl[i] = __float2bfloat16(v - __bfloat162float(hi));
}

// ---------------------------------------------------------------------------
// Kernel 1: deformable bilinear sampling -> bf16 hi/lo columns [k][n]
// ---------------------------------------------------------------------------
__global__ __launch_bounds__(256) void sample_kernel(
    const float* __restrict__ in, const float* __restrict__ off,
    const float* __restrict__ mask)
{
    const int n  = blockIdx.x * 256 + threadIdx.x;
    const int k  = blockIdx.y;
    const int b  = n >> 12;
    const int hw = n & 4095;
    const int h  = hw >> 6;
    const int w  = hw & 63;

    const float dy = off[((b * 18 + 2 * k)     << 12) + hw];
    const float dx = off[((b * 18 + 2 * k + 1) << 12) + hw];
    const float m  = mask[((b * 9 + k)         << 12) + hw];

    const float y = (float)h + (float)(k / 3 - 1) + dy;
    const float x = (float)w + (float)(k % 3 - 1) + dx;
    const float y0f = floorf(y), x0f = floorf(x);
    const int   y0 = (int)y0f,  x0 = (int)x0f;
    const float wy1 = y - y0f, wx1 = x - x0f;
    const float wy0 = 1.0f - wy1, wx0 = 1.0f - wx1;

    const bool vy0 = (y0 >= 0) && (y0 < Hd);
    const bool vy1 = (y0 + 1 >= 0) && (y0 + 1 < Hd);
    const bool vx0 = (x0 >= 0) && (x0 < Wd);
    const bool vx1 = (x0 + 1 >= 0) && (x0 + 1 < Wd);

    const float w00 = (vy0 && vx0) ? wy0 * wx0 * m : 0.0f;
    const float w01 = (vy0 && vx1) ? wy0 * wx1 * m : 0.0f;
    const float w10 = (vy1 && vx0) ? wy1 * wx0 * m : 0.0f;
    const float w11 = (vy1 && vx1) ? wy1 * wx1 * m : 0.0f;

    const int i00 = (vy0 && vx0) ? (y0       * Wd + x0    ) : 0;
    const int i01 = (vy0 && vx1) ? (y0       * Wd + x0 + 1) : 0;
    const int i10 = (vy1 && vx0) ? ((y0 + 1) * Wd + x0    ) : 0;
    const int i11 = (vy1 && vx1) ? ((y0 + 1) * Wd + x0 + 1) : 0;

    const float* __restrict__ p = in + (size_t)(b * Cd) * HW;
    size_t idx = (size_t)k * NTOT + n;

#pragma unroll 4
    for (int c = 0; c < Cd; ++c) {
        const float* pc = p + c * HW;
        float v = w00 * __ldg(pc + i00) + w01 * __ldg(pc + i01)
                + w10 * __ldg(pc + i10) + w11 * __ldg(pc + i11);
        __nv_bfloat16 hi = __float2bfloat16(v);
        g_colsh[idx] = hi;
        g_colsl[idx] = __float2bfloat16(v - __bfloat162float(hi));
        idx += (size_t)9 * NTOT;
    }
}

// ---------------------------------------------------------------------------
// Stage loader: cp.async one combined stage (Ah, Al, Bh, Bl)
// 2048 16B chunks / 256 threads = 8 per thread
// ---------------------------------------------------------------------------
__device__ __forceinline__ void load_stage(uint32_t sbuf, int s, int m0, int n0, int tid)
{
    const int k0 = s * BK;
#pragma unroll
    for (int j = 0; j < 8; ++j) {
        const int c = tid + j * 256;
        if (c < 1024) {               // A: hi then lo, 128 rows x 4 chunks each
            const int cc  = c & 511;
            const int row = cc >> 2, seg = cc & 3;
            const __nv_bfloat16* src = (c < 512 ? g_wh : g_wl) + (m0 + row) * KDIM + k0 + seg * 8;
            CP_ASYNC(sbuf + (c < 512 ? AH_OFF : AL_OFF) + row * A_ROW_B + seg * 16, src);
        } else {                      // B: hi then lo, 32 rows x 16 chunks each
            const int cc  = (c - 1024) & 511;
            const int row = cc >> 4, seg = cc & 15;
            const __nv_bfloat16* src = (c < 1536 ? g_colsh : g_colsl)
                                     + (size_t)(k0 + row) * NTOT + n0 + seg * 8;
            CP_ASYNC(sbuf + (c < 1536 ? BH_OFF : BL_OFF) + row * B_ROW_B + seg * 16, src);
        }
    }
    CP_COMMIT();
}

// ---------------------------------------------------------------------------
// Kernel 2: bf16x3 GEMM via mma.sync, single K sweep.
// grid (2 m-tiles, 128 n-tiles), 256 threads, warp tile 64x32.
// ---------------------------------------------------------------------------
__global__ __launch_bounds__(256, 2) void gemm_mma(
    const float* __restrict__ bias, float* __restrict__ out)
{
    extern __shared__ char smem[];
    const uint32_t sb = smem_u32(smem);
    const int tid = threadIdx.x;
    const int wid = tid >> 5;
    const int lid = tid & 31;
    const int wm  = wid >> 2;        // 0..1 -> 64-row warp tile
    const int wn  = wid & 3;         // 0..3 -> 32-col warp tile
    const int m0  = blockIdx.x * BM; // m fastest -> B L2 dedup
    const int n0  = blockIdx.y * BN;

    float acc[4][4][4];
#pragma unroll
    for (int i = 0; i < 4; ++i)
#pragma unroll
        for (int j = 0; j < 4; ++j)
#pragma unroll
            for (int r = 0; r < 4; ++r) acc[i][j][r] = 0.0f;

    // prologue
    load_stage(sb, 0, m0, n0, tid);
    CP_WAIT(0);
    __syncthreads();

    const uint32_t a_lane = (uint32_t)((lid & 15) * A_ROW_B + (lid >> 4) * 16);
    const uint32_t b_lane = (uint32_t)((lid & 15) * B_ROW_B + (lid >> 4) * 16);

    for (int s = 0; s < NSTG; ++s) {
        const uint32_t sbuf = sb + (uint32_t)(s & 1) * STAGE_B;
        const bool more = (s + 1 < NSTG);
        if (more) load_stage(sb + (uint32_t)((s + 1) & 1) * STAGE_B, s + 1, m0, n0, tid);

#pragma unroll
        for (int kkp = 0; kkp < 2; ++kkp) {
            // Ah frags
            uint32_t afh[4][4];
#pragma unroll
            for (int i = 0; i < 4; ++i) {
                const uint32_t addr = sbuf + AH_OFF + (uint32_t)((wm * 64 + i * 16) * A_ROW_B)
                                    + (uint32_t)(kkp * 32) + a_lane;
                LDMATRIX_X4(afh[i][0], afh[i][1], afh[i][2], afh[i][3], addr);
            }
            {   // Bh frags -> Ah*Bh and Al*Bh
                uint32_t bfh[2][4];
#pragma unroll
                for (int j2 = 0; j2 < 2; ++j2) {
                    const uint32_t addr = sbuf + BH_OFF + (uint32_t)(kkp * 16) * B_ROW_B
                                        + (uint32_t)((wn * 32 + j2 * 16) * 2) + b_lane;
                    LDMATRIX_X4T(bfh[j2][0], bfh[j2][1], bfh[j2][2], bfh[j2][3], addr);
                }
#pragma unroll
                for (int i = 0; i < 4; ++i)
#pragma unroll
                    for (int j = 0; j < 4; ++j)
                        MMA_BF16(acc[i][j], afh[i], bfh[j >> 1][(j & 1) * 2], bfh[j >> 1][(j & 1) * 2 + 1]);
                // Al frags
                uint32_t afl[4][4];
#pragma unroll
                for (int i = 0; i < 4; ++i) {
                    const uint32_t addr = sbuf + AL_OFF + (uint32_t)((wm * 64 + i * 16) * A_ROW_B)
                                        + (uint32_t)(kkp * 32) + a_lane;
                    LDMATRIX_X4(afl[i][0], afl[i][1], afl[i][2], afl[i][3], addr);
                }
#pragma unroll
                for (int i = 0; i < 4; ++i)
#pragma unroll
                    for (int j = 0; j < 4; ++j)
                        MMA_BF16(acc[i][j], afl[i], bfh[j >> 1][(j & 1) * 2], bfh[j >> 1][(j & 1) * 2 + 1]);
            }
            {   // Bl frags -> Ah*Bl
                uint32_t bfl[2][4];
#pragma unroll
                for (int j2 = 0; j2 < 2; ++j2) {
                    const uint32_t addr = sbuf + BL_OFF + (uint32_t)(kkp * 16) * B_ROW_B
                                        + (uint32_t)((wn * 32 + j2 * 16) * 2) + b_lane;
                    LDMATRIX_X4T(bfl[j2][0], bfl[j2][1], bfl[j2][2], bfl[j2][3], addr);
                }
#pragma unroll
                for (int i = 0; i < 4; ++i)
#pragma unroll
                    for (int j = 0; j < 4; ++j)
                        MMA_BF16(acc[i][j], afh[i], bfl[j >> 1][(j & 1) * 2], bfl[j >> 1][(j & 1) * 2 + 1]);
            }
        }

        if (more) CP_WAIT(0);
        __syncthreads();
    }

    // epilogue
    const int b   = n0 >> 12;
    const int hwb = n0 & 4095;
#pragma unroll
    for (int i = 0; i < 4; ++i) {
        const int o_lo = m0 + wm * 64 + i * 16 + (lid >> 2);
        const float bi0 = bias[o_lo];
        const float bi1 = bias[o_lo + 8];
#pragma unroll
        for (int j = 0; j < 4; ++j) {
            const int nc = hwb + wn * 32 + j * 8 + (lid & 3) * 2;
            float2 v0 = make_float2(acc[i][j][0] + bi0, acc[i][j][1] + bi0);
            float2 v1 = make_float2(acc[i][j][2] + bi1, acc[i][j][3] + bi1);
            *(float2*)(out + (((size_t)(b * COd + o_lo))     << 12) + nc) = v0;
            *(float2*)(out + (((size_t)(b * COd + o_lo + 8)) << 12) + nc) = v1;
        }
    }
}

// ---------------------------------------------------------------------------
// Kernel 3: GroupNorm partial sums. grid 512 (8 blocks per (b,g))
// ---------------------------------------------------------------------------
__global__ __launch_bounds__(256) void stats_kernel(const float* __restrict__ out)
{
    const int bg   = blockIdx.x >> 3;
    const int part = blockIdx.x & 7;
    const float* p = out + (size_t)bg * 65536 + part * 8192;

    float s = 0.0f, ss = 0.0f;
#pragma unroll
    for (int it = 0; it < 8; ++it) {
        float4 v = *(const float4*)(p + (threadIdx.x + it * 256) * 4);
        s  += v.x + v.y + v.z + v.w;
        ss += v.x * v.x + v.y * v.y + v.z * v.z + v.w * v.w;
    }
    __shared__ float sh_s[256], sh_q[256];
    sh_s[threadIdx.x] = s; sh_q[threadIdx.x] = ss;
    __syncthreads();
    for (int st = 128; st > 0; st >>= 1) {
        if (threadIdx.x < st) {
            sh_s[threadIdx.x] += sh_s[threadIdx.x + st];
            sh_q[threadIdx.x] += sh_q[threadIdx.x + st];
        }
        __syncthreads();
    }
    if (threadIdx.x == 0) g_part[blockIdx.x] = make_float2(sh_s[0], sh_q[0]);
}

// ---------------------------------------------------------------------------
// Kernel 4: normalize in place (deterministic finalize per block)
// ---------------------------------------------------------------------------
__global__ __launch_bounds__(256) void norm_kernel(
    float* __restrict__ out, const float* __restrict__ gamma,
    const float* __restrict__ beta)
{
    const int fi0 = blockIdx.x << 10;     // 1024 floats per block
    const int o   = (fi0 >> 12) & 255;
    const int b   = fi0 >> 20;
    const int bg  = b * 16 + (o >> 4);

    float s = 0.0f, q = 0.0f;
#pragma unroll
    for (int i = 0; i < 8; ++i) {
        float2 pp = g_part[bg * 8 + i];
        s += pp.x; q += pp.y;
    }
    const float cnt = 65536.0f;
    const float mu  = s / cnt;
    const float var = q / cnt - mu * mu;
    const float inv = rsqrtf(var + 1e-5f);
    const float ga  = gamma[o] * inv;
    const float be  = beta[o] - mu * ga;

    const int idx = (fi0 >> 2) + threadIdx.x;
    float4 v = ((const float4*)out)[idx];
    v.x = v.x * ga + be; v.y = v.y * ga + be;
    v.z = v.z * ga + be; v.w = v.w * ga + be;
    ((float4*)out)[idx] = v;
}

// ---------------------------------------------------------------------------
extern "C" void kernel_launch(void* const* d_in, const int* in_sizes, int n_in,
                              void* d_out, int out_size)
{
    const float* input  = (const float*)d_in[0];
    const float* offset = (const float*)d_in[1];
    const float* mask   = (const float*)d_in[2];
    const float* weight = (const float*)d_in[3];
    const float* bias   = (const float*)d_in[4];
    const float* gamma  = (const float*)d_in[5];
    const float* beta   = (const float*)d_in[6];
    float* out = (float*)d_out;

    cudaFuncSetAttribute(gemm_mma, cudaFuncAttributeMaxDynamicSharedMemorySize, SMEM_TOTAL);

    wprep_kernel<<<COd * KDIM / 256, 256>>>(weight);

    dim3 gs(NTOT / 256, 9);
    sample_kernel<<<gs, 256>>>(input, offset, mask);

    dim3 gg(COd / BM, NTOT / BN);   // m fastest -> B-tile L2 reuse
    gemm_mma<<<gg, 256, SMEM_TOTAL>>>(bias, out);

    stats_kernel<<<512, 256>>>(out);

    norm_kernel<<<Bd * COd * HW / 1024, 256>>>(out, gamma, beta);
}

// round 7
// speedup vs baseline: 1.5456x; 1.0203x over previous
#include <cuda_runtime.h>
#include <cuda_bf16.h>
#include <cstdint>

#define Hd   64
#define Wd   64
#define HW   4096
#define Bd   4
#define Cd   256
#define COd  256
#define KDIM 2304
#define NTOT 16384
#define NGRP 16
#define CPG  16

// GEMM tiling: CTA tile 128m x 256n x 32k, warp tile 64x64, 8 warps
#define BM 128
#define BN 256
#define BK 32
#define NSTG (KDIM / BK)       // 72 stages
// stage layout (bytes): Ah[128][80] Al[128][80] Bh[32][528] Bl[32][528]
#define A_ROW_B  80
#define B_ROW_B  528
#define AH_OFF   0
#define AL_OFF   10240
#define BH_OFF   20480
#define BL_OFF   37376
#define STAGE_B  54272
#define NBUF     3
#define SMEM_TOTAL (NBUF * STAGE_B)   // 162816

// im2col columns as bf16 hi/lo, layout [k=2304][n=16384]
__device__ __align__(256) __nv_bfloat16 g_colsh[(size_t)KDIM * NTOT];
__device__ __align__(256) __nv_bfloat16 g_colsl[(size_t)KDIM * NTOT];
// weights split to bf16 hi/lo, [256][2304]
__device__ __align__(256) __nv_bfloat16 g_wh[COd * KDIM];
__device__ __align__(256) __nv_bfloat16 g_wl[COd * KDIM];
// groupnorm partials
__device__ float2 g_part[512];

// ---------------------------------------------------------------------------
__device__ __forceinline__ uint32_t smem_u32(const void* p) {
    uint32_t a;
    asm("{ .reg .u64 t; cvta.to.shared.u64 t, %1; cvt.u32.u64 %0, t; }" : "=r"(a) : "l"(p));
    return a;
}
#define CP_ASYNC(dst, src) \
    asm volatile("cp.async.cg.shared.global [%0], [%1], 16;" :: "r"(dst), "l"(src))
#define CP_COMMIT() asm volatile("cp.async.commit_group;")
#define CP_WAIT(n)  asm volatile("cp.async.wait_group %0;" :: "n"(n))

#define LDMATRIX_X4(r0, r1, r2, r3, a) \
    asm volatile("ldmatrix.sync.aligned.m8n8.x4.shared.b16 {%0,%1,%2,%3}, [%4];" \
        : "=r"(r0), "=r"(r1), "=r"(r2), "=r"(r3) : "r"(a))
#define LDMATRIX_X4T(r0, r1, r2, r3, a) \
    asm volatile("ldmatrix.sync.aligned.m8n8.x4.trans.shared.b16 {%0,%1,%2,%3}, [%4];" \
        : "=r"(r0), "=r"(r1), "=r"(r2), "=r"(r3) : "r"(a))

#define MMA_BF16(d, a, b0v, b1v) \
    asm volatile("mma.sync.aligned.m16n8k16.row.col.f32.bf16.bf16.f32 " \
        "{%0,%1,%2,%3}, {%4,%5,%6,%7}, {%8,%9}, {%0,%1,%2,%3};" \
        : "+f"((d)[0]), "+f"((d)[1]), "+f"((d)[2]), "+f"((d)[3]) \
        : "r"((a)[0]), "r"((a)[1]), "r"((a)[2]), "r"((a)[3]), "r"(b0v), "r"(b1v))

// ---------------------------------------------------------------------------
// Kernel 0: split weights into bf16 hi/lo
// ---------------------------------------------------------------------------
__global__ __launch_bounds__(256) void wprep_kernel(const float* __restrict__ w) {
    int i = blockIdx.x * 256 + threadIdx.x;
    float v = w[i];
    __nv_bfloat16 hi = __float2bfloat16(v);
    g_wh[i] = hi;
    g_wl[i] = __float2bfloat16(v - __bfloat162float(hi));
}

// ---------------------------------------------------------------------------
// Kernel 1: deformable bilinear sampling -> bf16 hi/lo columns [k][n]
// ---------------------------------------------------------------------------
__global__ __launch_bounds__(256) void sample_kernel(
    const float* __restrict__ in, const float* __restrict__ off,
    const float* __restrict__ mask)
{
    const int n  = blockIdx.x * 256 + threadIdx.x;
    const int k  = blockIdx.y;
    const int b  = n >> 12;
    const int hw = n & 4095;
    const int h  = hw >> 6;
    const int w  = hw & 63;

    const float dy = off[((b * 18 + 2 * k)     << 12) + hw];
    const float dx = off[((b * 18 + 2 * k + 1) << 12) + hw];
    const float m  = mask[((b * 9 + k)         << 12) + hw];

    const float y = (float)h + (float)(k / 3 - 1) + dy;
    const float x = (float)w + (float)(k % 3 - 1) + dx;
    const float y0f = floorf(y), x0f = floorf(x);
    const int   y0 = (int)y0f,  x0 = (int)x0f;
    const float wy1 = y - y0f, wx1 = x - x0f;
    const float wy0 = 1.0f - wy1, wx0 = 1.0f - wx1;

    const bool vy0 = (y0 >= 0) && (y0 < Hd);
    const bool vy1 = (y0 + 1 >= 0) && (y0 + 1 < Hd);
    const bool vx0 = (x0 >= 0) && (x0 < Wd);
    const bool vx1 = (x0 + 1 >= 0) && (x0 + 1 < Wd);

    const float w00 = (vy0 && vx0) ? wy0 * wx0 * m : 0.0f;
    const float w01 = (vy0 && vx1) ? wy0 * wx1 * m : 0.0f;
    const float w10 = (vy1 && vx0) ? wy1 * wx0 * m : 0.0f;
    const float w11 = (vy1 && vx1) ? wy1 * wx1 * m : 0.0f;

    const int i00 = (vy0 && vx0) ? (y0       * Wd + x0    ) : 0;
    const int i01 = (vy0 && vx1) ? (y0       * Wd + x0 + 1) : 0;
    const int i10 = (vy1 && vx0) ? ((y0 + 1) * Wd + x0    ) : 0;
    const int i11 = (vy1 && vx1) ? ((y0 + 1) * Wd + x0 + 1) : 0;

    const float* __restrict__ p = in + (size_t)(b * Cd) * HW;
    size_t idx = (size_t)k * NTOT + n;

#pragma unroll 4
    for (int c = 0; c < Cd; ++c) {
        const float* pc = p + c * HW;
        float v = w00 * __ldg(pc + i00) + w01 * __ldg(pc + i01)
                + w10 * __ldg(pc + i10) + w11 * __ldg(pc + i11);
        __nv_bfloat16 hi = __float2bfloat16(v);
        g_colsh[idx] = hi;
        g_colsl[idx] = __float2bfloat16(v - __bfloat162float(hi));
        idx += (size_t)9 * NTOT;
    }
}

// ---------------------------------------------------------------------------
// Stage loader: cp.async one combined stage (Ah, Al, Bh, Bl)
// 3072 16B chunks / 256 threads = 12 per thread
// ---------------------------------------------------------------------------
__device__ __forceinline__ void load_stage(uint32_t sbuf, int s, int m0, int n0, int tid)
{
    const int k0 = s * BK;
#pragma unroll
    for (int j = 0; j < 12; ++j) {
        const int c = tid + j * 256;
        if (c < 1024) {               // A: hi then lo, 128 rows x 4 chunks each
            const int cc  = c & 511;
            const int row = cc >> 2, seg = cc & 3;
            const __nv_bfloat16* src = (c < 512 ? g_wh : g_wl) + (m0 + row) * KDIM + k0 + seg * 8;
            CP_ASYNC(sbuf + (c < 512 ? AH_OFF : AL_OFF) + row * A_ROW_B + seg * 16, src);
        } else {                      // B: hi then lo, 32 rows x 32 chunks each
            const int cc  = (c - 1024) & 1023;
            const int row = cc >> 5, seg = cc & 31;
            const __nv_bfloat16* src = (c < 2048 ? g_colsh : g_colsl)
                                     + (size_t)(k0 + row) * NTOT + n0 + seg * 8;
            CP_ASYNC(sbuf + (c < 2048 ? BH_OFF : BL_OFF) + row * B_ROW_B + seg * 16, src);
        }
    }
    CP_COMMIT();
}

// ---------------------------------------------------------------------------
// Kernel 2: bf16x3 GEMM via mma.sync, single K sweep.
// grid (2 m-tiles, 64 n-tiles), 256 threads, warp tile 64x64.
// 3 buffers, prefetch distance 2 (prefetch target is never the live buffer).
// ---------------------------------------------------------------------------
__global__ __launch_bounds__(256, 1) void gemm_mma(
    const float* __restrict__ bias, float* __restrict__ out)
{
    extern __shared__ char smem[];
    const uint32_t sb = smem_u32(smem);
    const int tid = threadIdx.x;
    const int wid = tid >> 5;
    const int lid = tid & 31;
    const int wm  = wid >> 2;        // 0..1 -> 64-row warp tile
    const int wn  = wid & 3;         // 0..3 -> 64-col warp tile
    const int m0  = blockIdx.x * BM; // m fastest -> B L2 dedup
    const int n0  = blockIdx.y * BN;

    float acc[4][8][4];
#pragma unroll
    for (int i = 0; i < 4; ++i)
#pragma unroll
        for (int j = 0; j < 8; ++j)
#pragma unroll
            for (int r = 0; r < 4; ++r) acc[i][j][r] = 0.0f;

    // prologue: stages 0, 1
    load_stage(sb, 0, m0, n0, tid);
    load_stage(sb + STAGE_B, 1, m0, n0, tid);

    const uint32_t a_lane = (uint32_t)((lid & 15) * A_ROW_B + (lid >> 4) * 16);
    const uint32_t b_lane = (uint32_t)((lid & 15) * B_ROW_B + (lid >> 4) * 16);

    for (int s = 0; s < NSTG; ++s) {
        // stage s arrived (in-order group completion); all warps done with the
        // buffer that the next prefetch will overwrite (read 2 iters ago).
        if (s + 2 < NSTG) { CP_WAIT(1); } else { CP_WAIT(0); }
        __syncthreads();
        if (s + 2 < NSTG)
            load_stage(sb + (uint32_t)((s + 2) % 3) * STAGE_B, s + 2, m0, n0, tid);

        const uint32_t sbuf = sb + (uint32_t)(s % 3) * STAGE_B;

#pragma unroll
        for (int kkp = 0; kkp < 2; ++kkp) {
            // Ah frags
            uint32_t afh[4][4];
#pragma unroll
            for (int i = 0; i < 4; ++i) {
                const uint32_t addr = sbuf + AH_OFF + (uint32_t)((wm * 64 + i * 16) * A_ROW_B)
                                    + (uint32_t)(kkp * 32) + a_lane;
                LDMATRIX_X4(afh[i][0], afh[i][1], afh[i][2], afh[i][3], addr);
            }
            {   // Bh frags -> Ah*Bh and Al*Bh
                uint32_t bfh[4][4];
#pragma unroll
                for (int j2 = 0; j2 < 4; ++j2) {
                    const uint32_t addr = sbuf + BH_OFF + (uint32_t)(kkp * 16) * B_ROW_B
                                        + (uint32_t)((wn * 64 + j2 * 16) * 2) + b_lane;
                    LDMATRIX_X4T(bfh[j2][0], bfh[j2][1], bfh[j2][2], bfh[j2][3], addr);
                }
#pragma unroll
                for (int i = 0; i < 4; ++i)
#pragma unroll
                    for (int j = 0; j < 8; ++j)
                        MMA_BF16(acc[i][j], afh[i], bfh[j >> 1][(j & 1) * 2], bfh[j >> 1][(j & 1) * 2 + 1]);
                // Al frags (reuse bfh)
                uint32_t afl[4][4];
#pragma unroll
                for (int i = 0; i < 4; ++i) {
                    const uint32_t addr = sbuf + AL_OFF + (uint32_t)((wm * 64 + i * 16) * A_ROW_B)
                                        + (uint32_t)(kkp * 32) + a_lane;
                    LDMATRIX_X4(afl[i][0], afl[i][1], afl[i][2], afl[i][3], addr);
                }
#pragma unroll
                for (int i = 0; i < 4; ++i)
#pragma unroll
                    for (int j = 0; j < 8; ++j)
                        MMA_BF16(acc[i][j], afl[i], bfh[j >> 1][(j & 1) * 2], bfh[j >> 1][(j & 1) * 2 + 1]);
            }
            {   // Bl frags -> Ah*Bl (reuse afh)
                uint32_t bfl[4][4];
#pragma unroll
                for (int j2 = 0; j2 < 4; ++j2) {
                    const uint32_t addr = sbuf + BL_OFF + (uint32_t)(kkp * 16) * B_ROW_B
                                        + (uint32_t)((wn * 64 + j2 * 16) * 2) + b_lane;
                    LDMATRIX_X4T(bfl[j2][0], bfl[j2][1], bfl[j2][2], bfl[j2][3], addr);
                }
#pragma unroll
                for (int i = 0; i < 4; ++i)
#pragma unroll
                    for (int j = 0; j < 8; ++j)
                        MMA_BF16(acc[i][j], afh[i], bfl[j >> 1][(j & 1) * 2], bfl[j >> 1][(j & 1) * 2 + 1]);
            }
        }
    }

    // epilogue
    const int b   = n0 >> 12;
    const int hwb = n0 & 4095;
#pragma unroll
    for (int i = 0; i < 4; ++i) {
        const int o_lo = m0 + wm * 64 + i * 16 + (lid >> 2);
        const float bi0 = bias[o_lo];
        const float bi1 = bias[o_lo + 8];
#pragma unroll
        for (int j = 0; j < 8; ++j) {
            const int nc = hwb + wn * 64 + j * 8 + (lid & 3) * 2;
            float2 v0 = make_float2(acc[i][j][0] + bi0, acc[i][j][1] + bi0);
            float2 v1 = make_float2(acc[i][j][2] + bi1, acc[i][j][3] + bi1);
            *(float2*)(out + (((size_t)(b * COd + o_lo))     << 12) + nc) = v0;
            *(float2*)(out + (((size_t)(b * COd + o_lo + 8)) << 12) + nc) = v1;
        }
    }
}

// ---------------------------------------------------------------------------
// Kernel 3: GroupNorm partial sums. grid 512 (8 blocks per (b,g))
// ---------------------------------------------------------------------------
__global__ __launch_bounds__(256) void stats_kernel(const float* __restrict__ out)
{
    const int bg   = blockIdx.x >> 3;
    const int part = blockIdx.x & 7;
    const float* p = out + (size_t)bg * 65536 + part * 8192;

    float s = 0.0f, ss = 0.0f;
#pragma unroll
    for (int it = 0; it < 8; ++it) {
        float4 v = *(const float4*)(p + (threadIdx.x + it * 256) * 4);
        s  += v.x + v.y + v.z + v.w;
        ss += v.x * v.x + v.y * v.y + v.z * v.z + v.w * v.w;
    }
    __shared__ float sh_s[256], sh_q[256];
    sh_s[threadIdx.x] = s; sh_q[threadIdx.x] = ss;
    __syncthreads();
    for (int st = 128; st > 0; st >>= 1) {
        if (threadIdx.x < st) {
            sh_s[threadIdx.x] += sh_s[threadIdx.x + st];
            sh_q[threadIdx.x] += sh_q[threadIdx.x + st];
        }
        __syncthreads();
    }
    if (threadIdx.x == 0) g_part[blockIdx.x] = make_float2(sh_s[0], sh_q[0]);
}

// ---------------------------------------------------------------------------
// Kernel 4: normalize in place (deterministic finalize per block)
// ---------------------------------------------------------------------------
__global__ __launch_bounds__(256) void norm_kernel(
    float* __restrict__ out, const float* __restrict__ gamma,
    const float* __restrict__ beta)
{
    const int fi0 = blockIdx.x << 10;     // 1024 floats per block
    const int o   = (fi0 >> 12) & 255;
    const int b   = fi0 >> 20;
    const int bg  = b * 16 + (o >> 4);

    float s = 0.0f, q = 0.0f;
#pragma unroll
    for (int i = 0; i < 8; ++i) {
        float2 pp = g_part[bg * 8 + i];
        s += pp.x; q += pp.y;
    }
    const float cnt = 65536.0f;
    const float mu  = s / cnt;
    const float var = q / cnt - mu * mu;
    const float inv = rsqrtf(var + 1e-5f);
    const float ga  = gamma[o] * inv;
    const float be  = beta[o] - mu * ga;

    const int idx = (fi0 >> 2) + threadIdx.x;
    float4 v = ((const float4*)out)[idx];
    v.x = v.x * ga + be; v.y = v.y * ga + be;
    v.z = v.z * ga + be; v.w = v.w * ga + be;
    ((float4*)out)[idx] = v;
}

// ---------------------------------------------------------------------------
extern "C" void kernel_launch(void* const* d_in, const int* in_sizes, int n_in,
                              void* d_out, int out_size)
{
    const float* input  = (const float*)d_in[0];
    const float* offset = (const float*)d_in[1];
    const float* mask   = (const float*)d_in[2];
    const float* weight = (const float*)d_in[3];
    const float* bias   = (const float*)d_in[4];
    const float* gamma  = (const float*)d_in[5];
    const float* beta   = (const float*)d_in[6];
    float* out = (float*)d_out;

    cudaFuncSetAttribute(gemm_mma, cudaFuncAttributeMaxDynamicSharedMemorySize, SMEM_TOTAL);

    wprep_kernel<<<COd * KDIM / 256, 256>>>(weight);

    dim3 gs(NTOT / 256, 9);
    sample_kernel<<<gs, 256>>>(input, offset, mask);

    dim3 gg(COd / BM, NTOT / BN);   // m fastest -> B-tile L2 reuse
    gemm_mma<<<gg, 256, SMEM_TOTAL>>>(bias, out);

    stats_kernel<<<512, 256>>>(out);

    norm_kernel<<<Bd * COd * HW / 1024, 256>>>(out, gamma, beta);
}

// round 8
// speedup vs baseline: 2.5015x; 1.6184x over previous
#include <cuda_runtime.h>
#include <cuda_fp16.h>
#include <cstdint>

#define Hd   64
#define Wd   64
#define HW   4096
#define Bd   4
#define Cd   256
#define COd  256
#define KDIM 2304
#define NTOT 16384
#define NGRP 16
#define CPG  16

// GEMM tiling: CTA tile 128m x 256n x 32k, warp tile 64x64, 8 warps
#define BM 128
#define BN 256
#define BK 32
#define NSTG (KDIM / BK)       // 72 stages
// stage layout (bytes): A[128][80] B[32][528]  (fp16, padded rows)
#define A_ROW_B  80
#define B_ROW_B  528
#define A_OFF    0
#define B_OFF    10240
#define STAGE_B  27136
#define NBUF     4
#define SMEM_TOTAL (NBUF * STAGE_B)   // 108544

// im2col columns fp16, layout [k=2304][n=16384]
__device__ __align__(256) __half g_cols[(size_t)KDIM * NTOT];
// weights fp16, [256][2304]
__device__ __align__(256) __half g_w[COd * KDIM];
// groupnorm partials
__device__ float2 g_part[512];

// ---------------------------------------------------------------------------
__device__ __forceinline__ uint32_t smem_u32(const void* p) {
    uint32_t a;
    asm("{ .reg .u64 t; cvta.to.shared.u64 t, %1; cvt.u32.u64 %0, t; }" : "=r"(a) : "l"(p));
    return a;
}
#define CP_ASYNC(dst, src) \
    asm volatile("cp.async.cg.shared.global [%0], [%1], 16;" :: "r"(dst), "l"(src))
#define CP_COMMIT() asm volatile("cp.async.commit_group;")
#define CP_WAIT(n)  asm volatile("cp.async.wait_group %0;" :: "n"(n))

#define LDMATRIX_X4(r0, r1, r2, r3, a) \
    asm volatile("ldmatrix.sync.aligned.m8n8.x4.shared.b16 {%0,%1,%2,%3}, [%4];" \
        : "=r"(r0), "=r"(r1), "=r"(r2), "=r"(r3) : "r"(a))
#define LDMATRIX_X4T(r0, r1, r2, r3, a) \
    asm volatile("ldmatrix.sync.aligned.m8n8.x4.trans.shared.b16 {%0,%1,%2,%3}, [%4];" \
        : "=r"(r0), "=r"(r1), "=r"(r2), "=r"(r3) : "r"(a))

#define MMA_F16(d, a, b0v, b1v) \
    asm volatile("mma.sync.aligned.m16n8k16.row.col.f32.f16.f16.f32 " \
        "{%0,%1,%2,%3}, {%4,%5,%6,%7}, {%8,%9}, {%0,%1,%2,%3};" \
        : "+f"((d)[0]), "+f"((d)[1]), "+f"((d)[2]), "+f"((d)[3]) \
        : "r"((a)[0]), "r"((a)[1]), "r"((a)[2]), "r"((a)[3]), "r"(b0v), "r"(b1v))

// ---------------------------------------------------------------------------
// Kernel 0: convert weights to fp16
// ---------------------------------------------------------------------------
__global__ __launch_bounds__(256) void wprep_kernel(const float* __restrict__ w) {
    int i = blockIdx.x * 256 + threadIdx.x;
    g_w[i] = __float2half_rn(w[i]);
}

// ---------------------------------------------------------------------------
// Kernel 1: deformable bilinear sampling -> fp16 columns [k][n]
// ---------------------------------------------------------------------------
__global__ __launch_bounds__(256) void sample_kernel(
    const float* __restrict__ in, const float* __restrict__ off,
    const float* __restrict__ mask)
{
    const int n  = blockIdx.x * 256 + threadIdx.x;
    const int k  = blockIdx.y;
    const int b  = n >> 12;
    const int hw = n & 4095;
    const int h  = hw >> 6;
    const int w  = hw & 63;

    const float dy = off[((b * 18 + 2 * k)     << 12) + hw];
    const float dx = off[((b * 18 + 2 * k + 1) << 12) + hw];
    const float m  = mask[((b * 9 + k)         << 12) + hw];

    const float y = (float)h + (float)(k / 3 - 1) + dy;
    const float x = (float)w + (float)(k % 3 - 1) + dx;
    const float y0f = floorf(y), x0f = floorf(x);
    const int   y0 = (int)y0f,  x0 = (int)x0f;
    const float wy1 = y - y0f, wx1 = x - x0f;
    const float wy0 = 1.0f - wy1, wx0 = 1.0f - wx1;

    const bool vy0 = (y0 >= 0) && (y0 < Hd);
    const bool vy1 = (y0 + 1 >= 0) && (y0 + 1 < Hd);
    const bool vx0 = (x0 >= 0) && (x0 < Wd);
    const bool vx1 = (x0 + 1 >= 0) && (x0 + 1 < Wd);

    const float w00 = (vy0 && vx0) ? wy0 * wx0 * m : 0.0f;
    const float w01 = (vy0 && vx1) ? wy0 * wx1 * m : 0.0f;
    const float w10 = (vy1 && vx0) ? wy1 * wx0 * m : 0.0f;
    const float w11 = (vy1 && vx1) ? wy1 * wx1 * m : 0.0f;

    const int i00 = (vy0 && vx0) ? (y0       * Wd + x0    ) : 0;
    const int i01 = (vy0 && vx1) ? (y0       * Wd + x0 + 1) : 0;
    const int i10 = (vy1 && vx0) ? ((y0 + 1) * Wd + x0    ) : 0;
    const int i11 = (vy1 && vx1) ? ((y0 + 1) * Wd + x0 + 1) : 0;

    const float* __restrict__ p = in + (size_t)(b * Cd) * HW;
    size_t idx = (size_t)k * NTOT + n;

#pragma unroll 4
    for (int c = 0; c < Cd; ++c) {
        const float* pc = p + c * HW;
        float v = w00 * __ldg(pc + i00) + w01 * __ldg(pc + i01)
                + w10 * __ldg(pc + i10) + w11 * __ldg(pc + i11);
        g_cols[idx] = __float2half_rn(v);
        idx += (size_t)9 * NTOT;
    }
}

// ---------------------------------------------------------------------------
// Stage loader: cp.async one stage (A, B). 1536 chunks / 256 thr = 6 each.
// ---------------------------------------------------------------------------
__device__ __forceinline__ void load_stage(uint32_t sbuf, int s, int m0, int n0, int tid)
{
    const int k0 = s * BK;
#pragma unroll
    for (int j = 0; j < 6; ++j) {
        const int c = tid + j * 256;
        if (c < 512) {                // A: 128 rows x 4 chunks
            const int row = c >> 2, seg = c & 3;
            const __half* src = g_w + (m0 + row) * KDIM + k0 + seg * 8;
            CP_ASYNC(sbuf + A_OFF + row * A_ROW_B + seg * 16, src);
        } else {                      // B: 32 rows x 32 chunks
            const int cc  = c - 512;
            const int row = cc >> 5, seg = cc & 31;
            const __half* src = g_cols + (size_t)(k0 + row) * NTOT + n0 + seg * 8;
            CP_ASYNC(sbuf + B_OFF + row * B_ROW_B + seg * 16, src);
        }
    }
    CP_COMMIT();
}

// ---------------------------------------------------------------------------
// Kernel 2: fp16 GEMM via mma.sync, single pass.
// grid (2 m-tiles, 64 n-tiles), 256 threads, warp tile 64x64.
// 4 buffers, prefetch distance 3.
// ---------------------------------------------------------------------------
__global__ __launch_bounds__(256, 1) void gemm_mma(
    const float* __restrict__ bias, float* __restrict__ out)
{
    extern __shared__ char smem[];
    const uint32_t sb = smem_u32(smem);
    const int tid = threadIdx.x;
    const int wid = tid >> 5;
    const int lid = tid & 31;
    const int wm  = wid >> 2;        // 0..1 -> 64-row warp tile
    const int wn  = wid & 3;         // 0..3 -> 64-col warp tile
    const int m0  = blockIdx.x * BM;
    const int n0  = blockIdx.y * BN;

    float acc[4][8][4];
#pragma unroll
    for (int i = 0; i < 4; ++i)
#pragma unroll
        for (int j = 0; j < 8; ++j)
#pragma unroll
            for (int r = 0; r < 4; ++r) acc[i][j][r] = 0.0f;

    // prologue: stages 0..2
    load_stage(sb, 0, m0, n0, tid);
    load_stage(sb + STAGE_B, 1, m0, n0, tid);
    load_stage(sb + 2 * STAGE_B, 2, m0, n0, tid);

    const uint32_t a_lane = (uint32_t)((lid & 15) * A_ROW_B + (lid >> 4) * 16);
    const uint32_t b_lane = (uint32_t)((lid & 15) * B_ROW_B + (lid >> 4) * 16);

    for (int s = 0; s < NSTG; ++s) {
        // stage s arrived; buffer (s+3)%4 (holding stage s-1) fully consumed.
        if (s + 3 < NSTG) { CP_WAIT(2); } else { CP_WAIT(0); }
        __syncthreads();
        if (s + 3 < NSTG)
            load_stage(sb + (uint32_t)((s + 3) & 3) * STAGE_B, s + 3, m0, n0, tid);

        const uint32_t sbuf = sb + (uint32_t)(s & 3) * STAGE_B;

#pragma unroll
        for (int kkp = 0; kkp < 2; ++kkp) {
            uint32_t af[4][4];
#pragma unroll
            for (int i = 0; i < 4; ++i) {
                const uint32_t addr = sbuf + A_OFF + (uint32_t)((wm * 64 + i * 16) * A_ROW_B)
                                    + (uint32_t)(kkp * 32) + a_lane;
                LDMATRIX_X4(af[i][0], af[i][1], af[i][2], af[i][3], addr);
            }
            uint32_t bf[4][4];
#pragma unroll
            for (int j2 = 0; j2 < 4; ++j2) {
                const uint32_t addr = sbuf + B_OFF + (uint32_t)(kkp * 16) * B_ROW_B
                                    + (uint32_t)((wn * 64 + j2 * 16) * 2) + b_lane;
                LDMATRIX_X4T(bf[j2][0], bf[j2][1], bf[j2][2], bf[j2][3], addr);
            }
#pragma unroll
            for (int i = 0; i < 4; ++i)
#pragma unroll
                for (int j = 0; j < 8; ++j)
                    MMA_F16(acc[i][j], af[i], bf[j >> 1][(j & 1) * 2], bf[j >> 1][(j & 1) * 2 + 1]);
        }
    }

    // epilogue
    const int b   = n0 >> 12;
    const int hwb = n0 & 4095;
#pragma unroll
    for (int i = 0; i < 4; ++i) {
        const int o_lo = m0 + wm * 64 + i * 16 + (lid >> 2);
        const float bi0 = bias[o_lo];
        const float bi1 = bias[o_lo + 8];
#pragma unroll
        for (int j = 0; j < 8; ++j) {
            const int nc = hwb + wn * 64 + j * 8 + (lid & 3) * 2;
            float2 v0 = make_float2(acc[i][j][0] + bi0, acc[i][j][1] + bi0);
            float2 v1 = make_float2(acc[i][j][2] + bi1, acc[i][j][3] + bi1);
            *(float2*)(out + (((size_t)(b * COd + o_lo))     << 12) + nc) = v0;
            *(float2*)(out + (((size_t)(b * COd + o_lo + 8)) << 12) + nc) = v1;
        }
    }
}

// ---------------------------------------------------------------------------
// Kernel 3: GroupNorm partial sums. grid 512 (8 blocks per (b,g))
// ---------------------------------------------------------------------------
__global__ __launch_bounds__(256) void stats_kernel(const float* __restrict__ out)
{
    const int bg   = blockIdx.x >> 3;
    const int part = blockIdx.x & 7;
    const float* p = out + (size_t)bg * 65536 + part * 8192;

    float s = 0.0f, ss = 0.0f;
#pragma unroll
    for (int it = 0; it < 8; ++it) {
        float4 v = *(const float4*)(p + (threadIdx.x + it * 256) * 4);
        s  += v.x + v.y + v.z + v.w;
        ss += v.x * v.x + v.y * v.y + v.z * v.z + v.w * v.w;
    }
    __shared__ float sh_s[256], sh_q[256];
    sh_s[threadIdx.x] = s; sh_q[threadIdx.x] = ss;
    __syncthreads();
    for (int st = 128; st > 0; st >>= 1) {
        if (threadIdx.x < st) {
            sh_s[threadIdx.x] += sh_s[threadIdx.x + st];
            sh_q[threadIdx.x] += sh_q[threadIdx.x + st];
        }
        __syncthreads();
    }
    if (threadIdx.x == 0) g_part[blockIdx.x] = make_float2(sh_s[0], sh_q[0]);
}

// ---------------------------------------------------------------------------
// Kernel 4: normalize in place (deterministic finalize per block)
// ---------------------------------------------------------------------------
__global__ __launch_bounds__(256) void norm_kernel(
    float* __restrict__ out, const float* __restrict__ gamma,
    const float* __restrict__ beta)
{
    const int fi0 = blockIdx.x << 10;     // 1024 floats per block
    const int o   = (fi0 >> 12) & 255;
    const int b   = fi0 >> 20;
    const int bg  = b * 16 + (o >> 4);

    float s = 0.0f, q = 0.0f;
#pragma unroll
    for (int i = 0; i < 8; ++i) {
        float2 pp = g_part[bg * 8 + i];
        s += pp.x; q += pp.y;
    }
    const float cnt = 65536.0f;
    const float mu  = s / cnt;
    const float var = q / cnt - mu * mu;
    const float inv = rsqrtf(var + 1e-5f);
    const float ga  = gamma[o] * inv;
    const float be  = beta[o] - mu * ga;

    const int idx = (fi0 >> 2) + threadIdx.x;
    float4 v = ((const float4*)out)[idx];
    v.x = v.x * ga + be; v.y = v.y * ga + be;
    v.z = v.z * ga + be; v.w = v.w * ga + be;
    ((float4*)out)[idx] = v;
}

// ---------------------------------------------------------------------------
extern "C" void kernel_launch(void* const* d_in, const int* in_sizes, int n_in,
                              void* d_out, int out_size)
{
    const float* input  = (const float*)d_in[0];
    const float* offset = (const float*)d_in[1];
    const float* mask   = (const float*)d_in[2];
    const float* weight = (const float*)d_in[3];
    const float* bias   = (const float*)d_in[4];
    const float* gamma  = (const float*)d_in[5];
    const float* beta   = (const float*)d_in[6];
    float* out = (float*)d_out;

    cudaFuncSetAttribute(gemm_mma, cudaFuncAttributeMaxDynamicSharedMemorySize, SMEM_TOTAL);

    wprep_kernel<<<COd * KDIM / 256, 256>>>(weight);

    dim3 gs(NTOT / 256, 9);
    sample_kernel<<<gs, 256>>>(input, offset, mask);

    dim3 gg(COd / BM, NTOT / BN);   // m fastest -> B-tile L2 reuse
    gemm_mma<<<gg, 256, SMEM_TOTAL>>>(bias, out);

    stats_kernel<<<512, 256>>>(out);

    norm_kernel<<<Bd * COd * HW / 1024, 256>>>(out, gamma, beta);
}

// round 9
// speedup vs baseline: 3.1936x; 1.2767x over previous
#include <cuda_runtime.h>
#include <cuda_fp16.h>
#include <cstdint>

#define Hd   64
#define Wd   64
#define HW   4096
#define Bd   4
#define Cd   256
#define COd  256
#define KDIM 2304
#define NTOT 16384
#define NGRP 16
#define CPG  16

// GEMM tiling: CTA tile 128m x 256n x 32k, warp tile 64x64, 8 warps
#define BM 128
#define BN 256
#define BK 32
#define NSTG (KDIM / BK)       // 72 stages
// stage layout (bytes): A[128 m][80] then B[256 n][80]  (fp16, padded rows)
#define A_ROW_B  80
#define B_ROW_B  80
#define A_OFF    0
#define B_OFF    10240
#define STAGE_B  30720
#define NBUF     4
#define SMEM_TOTAL (NBUF * STAGE_B)   // 122880

// input transposed to NHWC fp16: [b][hw][c]
__device__ __align__(256) __half g_inT[(size_t)Bd * HW * Cd];
// im2col columns fp16, layout [n][k'] with k' = kk*256 + c
__device__ __align__(256) __half g_cols[(size_t)NTOT * KDIM];
// weights fp16, [o][k'] with k' = kk*256 + c
__device__ __align__(256) __half g_w[COd * KDIM];
// groupnorm partials
__device__ float2 g_part[512];

// ---------------------------------------------------------------------------
__device__ __forceinline__ uint32_t smem_u32(const void* p) {
    uint32_t a;
    asm("{ .reg .u64 t; cvta.to.shared.u64 t, %1; cvt.u32.u64 %0, t; }" : "=r"(a) : "l"(p));
    return a;
}
#define CP_ASYNC(dst, src) \
    asm volatile("cp.async.cg.shared.global [%0], [%1], 16;" :: "r"(dst), "l"(src))
#define CP_COMMIT() asm volatile("cp.async.commit_group;")
#define CP_WAIT(n)  asm volatile("cp.async.wait_group %0;" :: "n"(n))

#define LDMATRIX_X4(r0, r1, r2, r3, a) \
    asm volatile("ldmatrix.sync.aligned.m8n8.x4.shared.b16 {%0,%1,%2,%3}, [%4];" \
        : "=r"(r0), "=r"(r1), "=r"(r2), "=r"(r3) : "r"(a))

#define MMA_F16(d, a, b0v, b1v) \
    asm volatile("mma.sync.aligned.m16n8k16.row.col.f32.f16.f16.f32 " \
        "{%0,%1,%2,%3}, {%4,%5,%6,%7}, {%8,%9}, {%0,%1,%2,%3};" \
        : "+f"((d)[0]), "+f"((d)[1]), "+f"((d)[2]), "+f"((d)[3]) \
        : "r"((a)[0]), "r"((a)[1]), "r"((a)[2]), "r"((a)[3]), "r"(b0v), "r"(b1v))

// ---------------------------------------------------------------------------
// Kernel 0a: weights fp16 with K permutation k' = kk*256 + c
// ---------------------------------------------------------------------------
__global__ __launch_bounds__(256) void wprep_kernel(const float* __restrict__ w) {
    int i = blockIdx.x * 256 + threadIdx.x;   // over 256*2304
    const int o  = i / KDIM;
    const int r  = i - o * KDIM;
    const int kk = r >> 8;
    const int c  = r & 255;
    g_w[i] = __float2half_rn(w[(o * Cd + c) * 9 + kk]);
}

// ---------------------------------------------------------------------------
// Kernel 0b: transpose input NCHW fp32 -> NHWC fp16
// grid (HW/32, C/32, B), block (32, 8), smem tile 32x33
// ---------------------------------------------------------------------------
__global__ __launch_bounds__(256) void tprep_kernel(const float* __restrict__ in) {
    __shared__ float tile[32][33];
    const int hw0 = blockIdx.x * 32;
    const int c0  = blockIdx.y * 32;
    const int b   = blockIdx.z;
    const int tx  = threadIdx.x, ty = threadIdx.y;

#pragma unroll
    for (int j = 0; j < 4; ++j) {
        const int c = c0 + ty + j * 8;
        tile[ty + j * 8][tx] = in[((size_t)(b * Cd + c)) * HW + hw0 + tx];
    }
    __syncthreads();
#pragma unroll
    for (int j = 0; j < 4; ++j) {
        const int hw = hw0 + ty + j * 8;
        g_inT[((size_t)(b * HW + hw)) * Cd + c0 + tx] = __float2half_rn(tile[tx][ty + j * 8]);
    }
}

// ---------------------------------------------------------------------------
// Kernel 1: deformable bilinear sampling, NHWC. One warp per site batch.
// Site = (kk, n). Reads 4 contiguous 512B corner vectors, writes 512B to cols.
// grid 2304 blocks x 256 thr; 8 warps x 8 sites each.
// ---------------------------------------------------------------------------
__global__ __launch_bounds__(256) void sample_kernel(
    const float* __restrict__ off, const float* __restrict__ mask)
{
    const int warp  = blockIdx.x * 8 + (threadIdx.x >> 5);
    const int lane  = threadIdx.x & 31;
    const int c0    = lane * 8;          // 8 halfs = 16B per lane
    const int site0 = warp * 8;

#pragma unroll
    for (int it = 0; it < 8; ++it) {
        const int site = site0 + it;
        const int n  = site & (NTOT - 1);
        const int kk = site >> 14;
        const int b  = n >> 12;
        const int hw = n & 4095;
        const int h  = hw >> 6;
        const int w  = hw & 63;

        const float dy = off[((b * 18 + 2 * kk)     << 12) + hw];
        const float dx = off[((b * 18 + 2 * kk + 1) << 12) + hw];
        const float m  = mask[((b * 9 + kk)         << 12) + hw];

        const float y = (float)h + (float)(kk / 3 - 1) + dy;
        const float x = (float)w + (float)(kk % 3 - 1) + dx;
        const float y0f = floorf(y), x0f = floorf(x);
        const int   y0 = (int)y0f,  x0 = (int)x0f;
        const float wy1 = y - y0f, wx1 = x - x0f;
        const float wy0 = 1.0f - wy1, wx0 = 1.0f - wx1;

        const bool vy0 = (y0 >= 0) && (y0 < Hd);
        const bool vy1 = (y0 + 1 >= 0) && (y0 + 1 < Hd);
        const bool vx0 = (x0 >= 0) && (x0 < Wd);
        const bool vx1 = (x0 + 1 >= 0) && (x0 + 1 < Wd);

        const float w00 = (vy0 && vx0) ? wy0 * wx0 * m : 0.0f;
        const float w01 = (vy0 && vx1) ? wy0 * wx1 * m : 0.0f;
        const float w10 = (vy1 && vx0) ? wy1 * wx0 * m : 0.0f;
        const float w11 = (vy1 && vx1) ? wy1 * wx1 * m : 0.0f;

        const int i00 = (vy0 && vx0) ? (y0       * Wd + x0    ) : 0;
        const int i01 = (vy0 && vx1) ? (y0       * Wd + x0 + 1) : 0;
        const int i10 = (vy1 && vx0) ? ((y0 + 1) * Wd + x0    ) : 0;
        const int i11 = (vy1 && vx1) ? ((y0 + 1) * Wd + x0 + 1) : 0;

        const __half* base = g_inT + ((size_t)b * HW) * Cd + c0;
        union { uint4 u; __half2 h[4]; } u00, u01, u10, u11, res;
        u00.u = *(const uint4*)(base + (size_t)i00 * Cd);
        u01.u = *(const uint4*)(base + (size_t)i01 * Cd);
        u10.u = *(const uint4*)(base + (size_t)i10 * Cd);
        u11.u = *(const uint4*)(base + (size_t)i11 * Cd);

#pragma unroll
        for (int j = 0; j < 4; ++j) {
            const float2 f00 = __half22float2(u00.h[j]);
            const float2 f01 = __half22float2(u01.h[j]);
            const float2 f10 = __half22float2(u10.h[j]);
            const float2 f11 = __half22float2(u11.h[j]);
            const float rx = w00 * f00.x + w01 * f01.x + w10 * f10.x + w11 * f11.x;
            const float ry = w00 * f00.y + w01 * f01.y + w10 * f10.y + w11 * f11.y;
            res.h[j] = __floats2half2_rn(rx, ry);
        }
        *(uint4*)(g_cols + (size_t)n * KDIM + kk * 256 + c0) = res.u;
    }
}

// ---------------------------------------------------------------------------
// Stage loader: cp.async one stage (A 512 chunks, B 1024 chunks), 6/thread
// ---------------------------------------------------------------------------
__device__ __forceinline__ void load_stage(uint32_t sbuf, int s, int m0, int n0, int tid)
{
    const int k0 = s * BK;
#pragma unroll
    for (int j = 0; j < 6; ++j) {
        const int c = tid + j * 256;
        if (c < 512) {                // A: 128 rows x 4 chunks
            const int row = c >> 2, seg = c & 3;
            const __half* src = g_w + (m0 + row) * KDIM + k0 + seg * 8;
            CP_ASYNC(sbuf + A_OFF + row * A_ROW_B + seg * 16, src);
        } else {                      // B: 256 n-rows x 4 chunks
            const int cc  = c - 512;
            const int row = cc >> 2, seg = cc & 3;
            const __half* src = g_cols + (size_t)(n0 + row) * KDIM + k0 + seg * 8;
            CP_ASYNC(sbuf + B_OFF + row * B_ROW_B + seg * 16, src);
        }
    }
    CP_COMMIT();
}

// ---------------------------------------------------------------------------
// Kernel 2: fp16 GEMM via mma.sync. B stored n-major -> non-trans ldmatrix.
// grid (2 m-tiles, 64 n-tiles), 256 threads, warp tile 64x64, 4 bufs dist 3.
// ---------------------------------------------------------------------------
__global__ __launch_bounds__(256, 1) void gemm_mma(
    const float* __restrict__ bias, float* __restrict__ out)
{
    extern __shared__ char smem[];
    const uint32_t sb = smem_u32(smem);
    const int tid = threadIdx.x;
    const int wid = tid >> 5;
    const int lid = tid & 31;
    const int wm  = wid >> 2;        // 0..1 -> 64-row warp tile
    const int wn  = wid & 3;         // 0..3 -> 64-col warp tile
    const int m0  = blockIdx.x * BM;
    const int n0  = blockIdx.y * BN;

    float acc[4][8][4];
#pragma unroll
    for (int i = 0; i < 4; ++i)
#pragma unroll
        for (int j = 0; j < 8; ++j)
#pragma unroll
            for (int r = 0; r < 4; ++r) acc[i][j][r] = 0.0f;

    // prologue: stages 0..2
    load_stage(sb, 0, m0, n0, tid);
    load_stage(sb + STAGE_B, 1, m0, n0, tid);
    load_stage(sb + 2 * STAGE_B, 2, m0, n0, tid);

    const uint32_t a_lane = (uint32_t)((lid & 15) * A_ROW_B + (lid >> 4) * 16);
    // B non-trans lanes: g0: n=l&7,k+0 | g1: n=l&7,k+16B | g2: n=8+(l&7),k+0 | g3: n=8+(l&7),k+16B
    const uint32_t b_lane = (uint32_t)((((lid >> 4) << 3) + (lid & 7)) * B_ROW_B
                                       + ((lid >> 3) & 1) * 16);

    for (int s = 0; s < NSTG; ++s) {
        if (s + 3 < NSTG) { CP_WAIT(2); } else { CP_WAIT(0); }
        __syncthreads();
        if (s + 3 < NSTG)
            load_stage(sb + (uint32_t)((s + 3) & 3) * STAGE_B, s + 3, m0, n0, tid);

        const uint32_t sbuf = sb + (uint32_t)(s & 3) * STAGE_B;

#pragma unroll
        for (int kkp = 0; kkp < 2; ++kkp) {
            uint32_t af[4][4];
#pragma unroll
            for (int i = 0; i < 4; ++i) {
                const uint32_t addr = sbuf + A_OFF + (uint32_t)((wm * 64 + i * 16) * A_ROW_B)
                                    + (uint32_t)(kkp * 32) + a_lane;
                LDMATRIX_X4(af[i][0], af[i][1], af[i][2], af[i][3], addr);
            }
            uint32_t bf[4][4];  // bf[j2] = {b0 n-oct0, b1 n-oct0, b0 n-oct1, b1 n-oct1}
#pragma unroll
            for (int j2 = 0; j2 < 4; ++j2) {
                const uint32_t addr = sbuf + B_OFF + (uint32_t)((wn * 64 + j2 * 16) * B_ROW_B)
                                    + (uint32_t)(kkp * 32) + b_lane;
                LDMATRIX_X4(bf[j2][0], bf[j2][1], bf[j2][2], bf[j2][3], addr);
            }
#pragma unroll
            for (int i = 0; i < 4; ++i)
#pragma unroll
                for (int j = 0; j < 8; ++j)
                    MMA_F16(acc[i][j], af[i], bf[j >> 1][(j & 1) * 2], bf[j >> 1][(j & 1) * 2 + 1]);
        }
    }

    // epilogue
    const int b   = n0 >> 12;
    const int hwb = n0 & 4095;
#pragma unroll
    for (int i = 0; i < 4; ++i) {
        const int o_lo = m0 + wm * 64 + i * 16 + (lid >> 2);
        const float bi0 = bias[o_lo];
        const float bi1 = bias[o_lo + 8];
#pragma unroll
        for (int j = 0; j < 8; ++j) {
            const int nc = hwb + wn * 64 + j * 8 + (lid & 3) * 2;
            float2 v0 = make_float2(acc[i][j][0] + bi0, acc[i][j][1] + bi0);
            float2 v1 = make_float2(acc[i][j][2] + bi1, acc[i][j][3] + bi1);
            *(float2*)(out + (((size_t)(b * COd + o_lo))     << 12) + nc) = v0;
            *(float2*)(out + (((size_t)(b * COd + o_lo + 8)) << 12) + nc) = v1;
        }
    }
}

// ---------------------------------------------------------------------------
// Kernel 3: GroupNorm partial sums. grid 512 (8 blocks per (b,g))
// ---------------------------------------------------------------------------
__global__ __launch_bounds__(256) void stats_kernel(const float* __restrict__ out)
{
    const int bg   = blockIdx.x >> 3;
    const int part = blockIdx.x & 7;
    const float* p = out + (size_t)bg * 65536 + part * 8192;

    float s = 0.0f, ss = 0.0f;
#pragma unroll
    for (int it = 0; it < 8; ++it) {
        float4 v = *(const float4*)(p + (threadIdx.x + it * 256) * 4);
        s  += v.x + v.y + v.z + v.w;
        ss += v.x * v.x + v.y * v.y + v.z * v.z + v.w * v.w;
    }
    __shared__ float sh_s[256], sh_q[256];
    sh_s[threadIdx.x] = s; sh_q[threadIdx.x] = ss;
    __syncthreads();
    for (int st = 128; st > 0; st >>= 1) {
        if (threadIdx.x < st) {
            sh_s[threadIdx.x] += sh_s[threadIdx.x + st];
            sh_q[threadIdx.x] += sh_q[threadIdx.x + st];
        }
        __syncthreads();
    }
    if (threadIdx.x == 0) g_part[blockIdx.x] = make_float2(sh_s[0], sh_q[0]);
}

// ---------------------------------------------------------------------------
// Kernel 4: normalize in place (deterministic finalize per block)
// ---------------------------------------------------------------------------
__global__ __launch_bounds__(256) void norm_kernel(
    float* __restrict__ out, const float* __restrict__ gamma,
    const float* __restrict__ beta)
{
    const int fi0 = blockIdx.x << 10;     // 1024 floats per block
    const int o   = (fi0 >> 12) & 255;
    const int b   = fi0 >> 20;
    const int bg  = b * 16 + (o >> 4);

    float s = 0.0f, q = 0.0f;
#pragma unroll
    for (int i = 0; i < 8; ++i) {
        float2 pp = g_part[bg * 8 + i];
        s += pp.x; q += pp.y;
    }
    const float cnt = 65536.0f;
    const float mu  = s / cnt;
    const float var = q / cnt - mu * mu;
    const float inv = rsqrtf(var + 1e-5f);
    const float ga  = gamma[o] * inv;
    const float be  = beta[o] - mu * ga;

    const int idx = (fi0 >> 2) + threadIdx.x;
    float4 v = ((const float4*)out)[idx];
    v.x = v.x * ga + be; v.y = v.y * ga + be;
    v.z = v.z * ga + be; v.w = v.w * ga + be;
    ((float4*)out)[idx] = v;
}

// ---------------------------------------------------------------------------
extern "C" void kernel_launch(void* const* d_in, const int* in_sizes, int n_in,
                              void* d_out, int out_size)
{
    const float* input  = (const float*)d_in[0];
    const float* offset = (const float*)d_in[1];
    const float* mask   = (const float*)d_in[2];
    const float* weight = (const float*)d_in[3];
    const float* bias   = (const float*)d_in[4];
    const float* gamma  = (const float*)d_in[5];
    const float* beta   = (const float*)d_in[6];
    float* out = (float*)d_out;

    cudaFuncSetAttribute(gemm_mma, cudaFuncAttributeMaxDynamicSharedMemorySize, SMEM_TOTAL);

    wprep_kernel<<<COd * KDIM / 256, 256>>>(weight);

    dim3 gt(HW / 32, Cd / 32, Bd);
    tprep_kernel<<<gt, dim3(32, 8)>>>(input);

    sample_kernel<<<2304, 256>>>(offset, mask);

    dim3 gg(COd / BM, NTOT / BN);   // m fastest -> B-tile L2 reuse
    gemm_mma<<<gg, 256, SMEM_TOTAL>>>(bias, out);

    stats_kernel<<<512, 256>>>(out);

    norm_kernel<<<Bd * COd * HW / 1024, 256>>>(out, gamma, beta);
}

// round 10
// speedup vs baseline: 3.2914x; 1.0306x over previous
#include <cuda_runtime.h>
#include <cuda_fp16.h>
#include <cstdint>

#define Hd   64
#define Wd   64
#define HW   4096
#define Bd   4
#define Cd   256
#define COd  256
#define KDIM 2304
#define NTOT 16384
#define NGRP 16
#define CPG  16

// GEMM tiling: CTA tile 128m x 128n x 32k, warp tile 64x32, 8 warps, 2 CTA/SM
#define BM 128
#define BN 128
#define BK 32
#define NSTG (KDIM / BK)       // 72 stages
// stage layout (bytes): A[128 m][80] then B[128 n][80]  (fp16, padded rows)
#define A_ROW_B  80
#define B_ROW_B  80
#define A_OFF    0
#define B_OFF    10240
#define STAGE_B  20480
#define NBUF     4
#define SMEM_TOTAL (NBUF * STAGE_B)   // 81920

// input transposed to NHWC fp16: [b][hw][c]
__device__ __align__(256) __half g_inT[(size_t)Bd * HW * Cd];
// im2col columns fp16, layout [n][k'] with k' = kk*256 + c
__device__ __align__(256) __half g_cols[(size_t)NTOT * KDIM];
// weights fp16, [o][k'] with k' = kk*256 + c
__device__ __align__(256) __half g_w[COd * KDIM];
// groupnorm partials
__device__ float2 g_part[512];

// ---------------------------------------------------------------------------
__device__ __forceinline__ uint32_t smem_u32(const void* p) {
    uint32_t a;
    asm("{ .reg .u64 t; cvta.to.shared.u64 t, %1; cvt.u32.u64 %0, t; }" : "=r"(a) : "l"(p));
    return a;
}
#define CP_ASYNC(dst, src) \
    asm volatile("cp.async.cg.shared.global [%0], [%1], 16;" :: "r"(dst), "l"(src))
#define CP_COMMIT() asm volatile("cp.async.commit_group;")
#define CP_WAIT(n)  asm volatile("cp.async.wait_group %0;" :: "n"(n))

#define LDMATRIX_X4(r0, r1, r2, r3, a) \
    asm volatile("ldmatrix.sync.aligned.m8n8.x4.shared.b16 {%0,%1,%2,%3}, [%4];" \
        : "=r"(r0), "=r"(r1), "=r"(r2), "=r"(r3) : "r"(a))

#define MMA_F16(d, a, b0v, b1v) \
    asm volatile("mma.sync.aligned.m16n8k16.row.col.f32.f16.f16.f32 " \
        "{%0,%1,%2,%3}, {%4,%5,%6,%7}, {%8,%9}, {%0,%1,%2,%3};" \
        : "+f"((d)[0]), "+f"((d)[1]), "+f"((d)[2]), "+f"((d)[3]) \
        : "r"((a)[0]), "r"((a)[1]), "r"((a)[2]), "r"((a)[3]), "r"(b0v), "r"(b1v))

// ---------------------------------------------------------------------------
// Kernel 0a: weights fp16 with K permutation k' = kk*256 + c
// ---------------------------------------------------------------------------
__global__ __launch_bounds__(256) void wprep_kernel(const float* __restrict__ w) {
    int i = blockIdx.x * 256 + threadIdx.x;   // over 256*2304
    const int o  = i / KDIM;
    const int r  = i - o * KDIM;
    const int kk = r >> 8;
    const int c  = r & 255;
    g_w[i] = __float2half_rn(w[(o * Cd + c) * 9 + kk]);
}

// ---------------------------------------------------------------------------
// Kernel 0b: transpose input NCHW fp32 -> NHWC fp16
// ---------------------------------------------------------------------------
__global__ __launch_bounds__(256) void tprep_kernel(const float* __restrict__ in) {
    __shared__ float tile[32][33];
    const int hw0 = blockIdx.x * 32;
    const int c0  = blockIdx.y * 32;
    const int b   = blockIdx.z;
    const int tx  = threadIdx.x, ty = threadIdx.y;

#pragma unroll
    for (int j = 0; j < 4; ++j) {
        const int c = c0 + ty + j * 8;
        tile[ty + j * 8][tx] = in[((size_t)(b * Cd + c)) * HW + hw0 + tx];
    }
    __syncthreads();
#pragma unroll
    for (int j = 0; j < 4; ++j) {
        const int hw = hw0 + ty + j * 8;
        g_inT[((size_t)(b * HW + hw)) * Cd + c0 + tx] = __float2half_rn(tile[tx][ty + j * 8]);
    }
}

// ---------------------------------------------------------------------------
// Kernel 1: deformable bilinear sampling, NHWC. One warp per site.
// ---------------------------------------------------------------------------
__global__ __launch_bounds__(256) void sample_kernel(
    const float* __restrict__ off, const float* __restrict__ mask)
{
    const int warp  = blockIdx.x * 8 + (threadIdx.x >> 5);
    const int lane  = threadIdx.x & 31;
    const int c0    = lane * 8;          // 8 halfs = 16B per lane
    const int site0 = warp * 8;

#pragma unroll
    for (int it = 0; it < 8; ++it) {
        const int site = site0 + it;
        const int n  = site & (NTOT - 1);
        const int kk = site >> 14;
        const int b  = n >> 12;
        const int hw = n & 4095;
        const int h  = hw >> 6;
        const int w  = hw & 63;

        const float dy = off[((b * 18 + 2 * kk)     << 12) + hw];
        const float dx = off[((b * 18 + 2 * kk + 1) << 12) + hw];
        const float m  = mask[((b * 9 + kk)         << 12) + hw];

        const float y = (float)h + (float)(kk / 3 - 1) + dy;
        const float x = (float)w + (float)(kk % 3 - 1) + dx;
        const float y0f = floorf(y), x0f = floorf(x);
        const int   y0 = (int)y0f,  x0 = (int)x0f;
        const float wy1 = y - y0f, wx1 = x - x0f;
        const float wy0 = 1.0f - wy1, wx0 = 1.0f - wx1;

        const bool vy0 = (y0 >= 0) && (y0 < Hd);
        const bool vy1 = (y0 + 1 >= 0) && (y0 + 1 < Hd);
        const bool vx0 = (x0 >= 0) && (x0 < Wd);
        const bool vx1 = (x0 + 1 >= 0) && (x0 + 1 < Wd);

        const float w00 = (vy0 && vx0) ? wy0 * wx0 * m : 0.0f;
        const float w01 = (vy0 && vx1) ? wy0 * wx1 * m : 0.0f;
        const float w10 = (vy1 && vx0) ? wy1 * wx0 * m : 0.0f;
        const float w11 = (vy1 && vx1) ? wy1 * wx1 * m : 0.0f;

        const int i00 = (vy0 && vx0) ? (y0       * Wd + x0    ) : 0;
        const int i01 = (vy0 && vx1) ? (y0       * Wd + x0 + 1) : 0;
        const int i10 = (vy1 && vx0) ? ((y0 + 1) * Wd + x0    ) : 0;
        const int i11 = (vy1 && vx1) ? ((y0 + 1) * Wd + x0 + 1) : 0;

        const __half* base = g_inT + ((size_t)b * HW) * Cd + c0;
        union { uint4 u; __half2 h[4]; } u00, u01, u10, u11, res;
        u00.u = *(const uint4*)(base + (size_t)i00 * Cd);
        u01.u = *(const uint4*)(base + (size_t)i01 * Cd);
        u10.u = *(const uint4*)(base + (size_t)i10 * Cd);
        u11.u = *(const uint4*)(base + (size_t)i11 * Cd);

#pragma unroll
        for (int j = 0; j < 4; ++j) {
            const float2 f00 = __half22float2(u00.h[j]);
            const float2 f01 = __half22float2(u01.h[j]);
            const float2 f10 = __half22float2(u10.h[j]);
            const float2 f11 = __half22float2(u11.h[j]);
            const float rx = w00 * f00.x + w01 * f01.x + w10 * f10.x + w11 * f11.x;
            const float ry = w00 * f00.y + w01 * f01.y + w10 * f10.y + w11 * f11.y;
            res.h[j] = __floats2half2_rn(rx, ry);
        }
        *(uint4*)(g_cols + (size_t)n * KDIM + kk * 256 + c0) = res.u;
    }
}

// ---------------------------------------------------------------------------
// Stage loader: cp.async one stage (A 512 + B 512 chunks), 4 per thread
// ---------------------------------------------------------------------------
__device__ __forceinline__ void load_stage(uint32_t sbuf, int s, int m0, int n0, int tid)
{
    const int k0 = s * BK;
#pragma unroll
    for (int j = 0; j < 4; ++j) {
        const int c = tid + j * 256;
        if (c < 512) {                // A: 128 rows x 4 chunks
            const int row = c >> 2, seg = c & 3;
            const __half* src = g_w + (m0 + row) * KDIM + k0 + seg * 8;
            CP_ASYNC(sbuf + A_OFF + row * A_ROW_B + seg * 16, src);
        } else {                      // B: 128 n-rows x 4 chunks
            const int cc  = c - 512;
            const int row = cc >> 2, seg = cc & 3;
            const __half* src = g_cols + (size_t)(n0 + row) * KDIM + k0 + seg * 8;
            CP_ASYNC(sbuf + B_OFF + row * B_ROW_B + seg * 16, src);
        }
    }
    CP_COMMIT();
}

// ---------------------------------------------------------------------------
// Kernel 2: fp16 GEMM via mma.sync. B n-major -> non-trans ldmatrix.
// grid (2 m-tiles, 128 n-tiles), 256 threads, warp tile 64x32, 2 CTA/SM.
// ---------------------------------------------------------------------------
__global__ __launch_bounds__(256, 2) void gemm_mma(
    const float* __restrict__ bias, float* __restrict__ out)
{
    extern __shared__ char smem[];
    const uint32_t sb = smem_u32(smem);
    const int tid = threadIdx.x;
    const int wid = tid >> 5;
    const int lid = tid & 31;
    const int wm  = wid >> 2;        // 0..1 -> 64-row warp tile
    const int wn  = wid & 3;         // 0..3 -> 32-col warp tile
    const int m0  = blockIdx.x * BM;
    const int n0  = blockIdx.y * BN;

    float acc[4][4][4];
#pragma unroll
    for (int i = 0; i < 4; ++i)
#pragma unroll
        for (int j = 0; j < 4; ++j)
#pragma unroll
            for (int r = 0; r < 4; ++r) acc[i][j][r] = 0.0f;

    // prologue: stages 0..2
    load_stage(sb, 0, m0, n0, tid);
    load_stage(sb + STAGE_B, 1, m0, n0, tid);
    load_stage(sb + 2 * STAGE_B, 2, m0, n0, tid);

    const uint32_t a_lane = (uint32_t)((lid & 15) * A_ROW_B + (lid >> 4) * 16);
    // B non-trans lanes: g0/g1 n-oct0 k+0/k+16B, g2/g3 n-oct1
    const uint32_t b_lane = (uint32_t)((((lid >> 4) << 3) + (lid & 7)) * B_ROW_B
                                       + ((lid >> 3) & 1) * 16);

    for (int s = 0; s < NSTG; ++s) {
        if (s + 3 < NSTG) { CP_WAIT(2); } else { CP_WAIT(0); }
        __syncthreads();
        if (s + 3 < NSTG)
            load_stage(sb + (uint32_t)((s + 3) & 3) * STAGE_B, s + 3, m0, n0, tid);

        const uint32_t sbuf = sb + (uint32_t)(s & 3) * STAGE_B;

#pragma unroll
        for (int kkp = 0; kkp < 2; ++kkp) {
            uint32_t af[4][4];
#pragma unroll
            for (int i = 0; i < 4; ++i) {
                const uint32_t addr = sbuf + A_OFF + (uint32_t)((wm * 64 + i * 16) * A_ROW_B)
                                    + (uint32_t)(kkp * 32) + a_lane;
                LDMATRIX_X4(af[i][0], af[i][1], af[i][2], af[i][3], addr);
            }
            uint32_t bf[2][4];
#pragma unroll
            for (int j2 = 0; j2 < 2; ++j2) {
                const uint32_t addr = sbuf + B_OFF + (uint32_t)((wn * 32 + j2 * 16) * B_ROW_B)
                                    + (uint32_t)(kkp * 32) + b_lane;
                LDMATRIX_X4(bf[j2][0], bf[j2][1], bf[j2][2], bf[j2][3], addr);
            }
#pragma unroll
            for (int i = 0; i < 4; ++i)
#pragma unroll
                for (int j = 0; j < 4; ++j)
                    MMA_F16(acc[i][j], af[i], bf[j >> 1][(j & 1) * 2], bf[j >> 1][(j & 1) * 2 + 1]);
        }
    }

    // epilogue
    const int b   = n0 >> 12;
    const int hwb = n0 & 4095;
#pragma unroll
    for (int i = 0; i < 4; ++i) {
        const int o_lo = m0 + wm * 64 + i * 16 + (lid >> 2);
        const float bi0 = bias[o_lo];
        const float bi1 = bias[o_lo + 8];
#pragma unroll
        for (int j = 0; j < 4; ++j) {
            const int nc = hwb + wn * 32 + j * 8 + (lid & 3) * 2;
            float2 v0 = make_float2(acc[i][j][0] + bi0, acc[i][j][1] + bi0);
            float2 v1 = make_float2(acc[i][j][2] + bi1, acc[i][j][3] + bi1);
            *(float2*)(out + (((size_t)(b * COd + o_lo))     << 12) + nc) = v0;
            *(float2*)(out + (((size_t)(b * COd + o_lo + 8)) << 12) + nc) = v1;
        }
    }
}

// ---------------------------------------------------------------------------
// Kernel 3: GroupNorm partial sums. grid 512 (8 blocks per (b,g))
// ---------------------------------------------------------------------------
__global__ __launch_bounds__(256) void stats_kernel(const float* __restrict__ out)
{
    const int bg   = blockIdx.x >> 3;
    const int part = blockIdx.x & 7;
    const float* p = out + (size_t)bg * 65536 + part * 8192;

    float s = 0.0f, ss = 0.0f;
#pragma unroll
    for (int it = 0; it < 8; ++it) {
        float4 v = *(const float4*)(p + (threadIdx.x + it * 256) * 4);
        s  += v.x + v.y + v.z + v.w;
        ss += v.x * v.x + v.y * v.y + v.z * v.z + v.w * v.w;
    }
    __shared__ float sh_s[256], sh_q[256];
    sh_s[threadIdx.x] = s; sh_q[threadIdx.x] = ss;
    __syncthreads();
    for (int st = 128; st > 0; st >>= 1) {
        if (threadIdx.x < st) {
            sh_s[threadIdx.x] += sh_s[threadIdx.x + st];
            sh_q[threadIdx.x] += sh_q[threadIdx.x + st];
        }
        __syncthreads();
    }
    if (threadIdx.x == 0) g_part[blockIdx.x] = make_float2(sh_s[0], sh_q[0]);
}

// ---------------------------------------------------------------------------
// Kernel 4: normalize in place (deterministic finalize per block)
// ---------------------------------------------------------------------------
__global__ __launch_bounds__(256) void norm_kernel(
    float* __restrict__ out, const float* __restrict__ gamma,
    const float* __restrict__ beta)
{
    const int fi0 = blockIdx.x << 10;     // 1024 floats per block
    const int o   = (fi0 >> 12) & 255;
    const int b   = fi0 >> 20;
    const int bg  = b * 16 + (o >> 4);

    float s = 0.0f, q = 0.0f;
#pragma unroll
    for (int i = 0; i < 8; ++i) {
        float2 pp = g_part[bg * 8 + i];
        s += pp.x; q += pp.y;
    }
    const float cnt = 65536.0f;
    const float mu  = s / cnt;
    const float var = q / cnt - mu * mu;
    const float inv = rsqrtf(var + 1e-5f);
    const float ga  = gamma[o] * inv;
    const float be  = beta[o] - mu * ga;

    const int idx = (fi0 >> 2) + threadIdx.x;
    float4 v = ((const float4*)out)[idx];
    v.x = v.x * ga + be; v.y = v.y * ga + be;
    v.z = v.z * ga + be; v.w = v.w * ga + be;
    ((float4*)out)[idx] = v;
}

// ---------------------------------------------------------------------------
extern "C" void kernel_launch(void* const* d_in, const int* in_sizes, int n_in,
                              void* d_out, int out_size)
{
    const float* input  = (const float*)d_in[0];
    const float* offset = (const float*)d_in[1];
    const float* mask   = (const float*)d_in[2];
    const float* weight = (const float*)d_in[3];
    const float* bias   = (const float*)d_in[4];
    const float* gamma  = (const float*)d_in[5];
    const float* beta   = (const float*)d_in[6];
    float* out = (float*)d_out;

    cudaFuncSetAttribute(gemm_mma, cudaFuncAttributeMaxDynamicSharedMemorySize, SMEM_TOTAL);

    wprep_kernel<<<COd * KDIM / 256, 256>>>(weight);

    dim3 gt(HW / 32, Cd / 32, Bd);
    tprep_kernel<<<gt, dim3(32, 8)>>>(input);

    sample_kernel<<<2304, 256>>>(offset, mask);

    dim3 gg(COd / BM, NTOT / BN);   // m fastest -> B-tile L2 reuse
    gemm_mma<<<gg, 256, SMEM_TOTAL>>>(bias, out);

    stats_kernel<<<512, 256>>>(out);

    norm_kernel<<<Bd * COd * HW / 1024, 256>>>(out, gamma, beta);
}